// round 11
// baseline (speedup 1.0000x reference)
#include <cuda_runtime.h>
#include <cuda_fp16.h>
#include <cfloat>
#include <cstdint>

#define N_NODES 50000
#define IN_DIM  1024
#define E_EDGES 100000
#define NUM_REL 40
#define HEADS   4
#define OUT_DIM 200
#define HID     800
#define BATCH   8192
#define NEG_SLOPE 0.2f

#define BM 128
#define BN 64
#define BK 32
#define NCHUNK (IN_DIM / BK)            // 32
#define NT_M ((N_NODES + BM - 1) / BM)  // 391 (max; CTAs early-exit past len)
#define NT_N 13
#define PAD_N (NT_N * BN)               // 832

#define A_STRIDE 80
#define A_VER_SZ (128 * A_STRIDE)
#define B_VER_SZ (64 * A_STRIDE)
#define SA_OFF(buf) ((buf) * A_VER_SZ)
#define SB_OFF(buf) (2 * A_VER_SZ + (buf) * B_VER_SZ)
#define SM_TOT (2 * A_VER_SZ + 2 * B_VER_SZ)   // 30720

#define SPLITA_BLOCKS 592
#define SPLITB_BLOCKS ((IN_DIM / 32) * (PAD_N / 32))
#define MAX_OUT (2 * BATCH)             // 16384

// ---------------- scratch (device globals) ----------------
__device__ __align__(16) float g_h  [(size_t)N_NODES * HID];   // compacted h rows
__device__ __align__(16) float g_out[(size_t)N_NODES * HID];   // node-indexed
__device__ __align__(16) __half g_Ah[(size_t)N_NODES * IN_DIM];
__device__ __align__(16) __half g_Bh[(size_t)PAD_N * IN_DIM];
__device__ __align__(16) float g_csrc[IN_DIM * HEADS];
__device__ __align__(16) float g_cdst[IN_DIM * HEADS];
__device__ __align__(16) float g_ssrc  [N_NODES * HEADS];
__device__ __align__(16) float g_sdst  [N_NODES * HEADS];
__device__ float g_rlog  [NUM_REL * HEADS];
__device__ int   g_cnt   [N_NODES];
__device__ int   g_rowptr[N_NODES + 1];
__device__ int   g_cursor[N_NODES];
__device__ int   g_csre  [E_EDGES];
__device__ unsigned char g_need_out[N_NODES];   // monotone marks (deterministic per input)
__device__ unsigned char g_need_h  [N_NODES];
__device__ int   g_hidx  [N_NODES];
__device__ int   g_hlist [N_NODES];
__device__ int   g_ulist [N_NODES];
__device__ int   g_olist [MAX_OUT];
__device__ int   g_hcount;
__device__ int   g_ucount;
__device__ int   g_ocount;
__device__ int   g_is64;

// ---------------- helpers ----------------
__device__ __forceinline__ int load_idx(const void* p, int i) {
    if (g_is64) return (int)((const long long*)p)[i];
    return ((const int*)p)[i];
}
__device__ __forceinline__ float warp_reduce(float v) {
    #pragma unroll
    for (int o = 16; o > 0; o >>= 1) v += __shfl_down_sync(0xffffffffu, v, o);
    return v;
}
__device__ __forceinline__ uint32_t smem_u32(const void* p) {
    uint32_t a;
    asm("{ .reg .u64 t; cvta.to.shared.u64 t, %1; cvt.u32.u64 %0, t; }" : "=r"(a) : "l"(p));
    return a;
}
__device__ __forceinline__ void cp_async16(uint32_t s, const void* g) {
    asm volatile("cp.async.cg.shared.global [%0], [%1], 16;" :: "r"(s), "l"(g));
}
__device__ __forceinline__ void cp_commit() {
    asm volatile("cp.async.commit_group;" ::: "memory");
}
template<int NN> __device__ __forceinline__ void cp_wait() {
    asm volatile("cp.async.wait_group %0;" :: "n"(NN) : "memory");
}
__device__ __forceinline__ void ldm_x4(uint32_t* r, uint32_t addr) {
    asm volatile("ldmatrix.sync.aligned.m8n8.x4.shared.b16 {%0,%1,%2,%3}, [%4];"
                 : "=r"(r[0]), "=r"(r[1]), "=r"(r[2]), "=r"(r[3]) : "r"(addr));
}
__device__ __forceinline__ void mma16816(float* d, const uint32_t* a, const uint32_t* b) {
    asm volatile(
        "mma.sync.aligned.m16n8k16.row.col.f32.f16.f16.f32 "
        "{%0,%1,%2,%3}, {%4,%5,%6,%7}, {%8,%9}, {%0,%1,%2,%3};"
        : "+f"(d[0]), "+f"(d[1]), "+f"(d[2]), "+f"(d[3])
        : "r"(a[0]), "r"(a[1]), "r"(a[2]), "r"(a[3]), "r"(b[0]), "r"(b[1]));
}

// ---------------- 1) init + dtype detect + mark distmult endpoints ----------------
// Flags are monotone marks: pure function of constant inputs, so no re-zeroing
// needed across replays (module-load zeros cover the first run).
__global__ void init_mark_kernel(const void* __restrict__ si, const void* __restrict__ di) {
    __shared__ int s_is64;
    const int t = threadIdx.x;
    const int tid = blockIdx.x * blockDim.x + t;
    if (t == 0) {
        const long long* p = (const long long*)si;
        int ok = 1;
        for (int i = 0; i < 64; i++) {
            long long v = p[i];
            if (v < 0 || v >= N_NODES) { ok = 0; break; }
        }
        s_is64 = ok;
        if (blockIdx.x == 0) g_is64 = ok;
    }
    if (tid < N_NODES) g_cnt[tid] = 0;
    if (tid == 0) { g_hcount = 0; g_ucount = 0; g_ocount = 0; }
    __syncthreads();
    const int is64 = s_is64;
    if (tid < BATCH) {
        int n = is64 ? (int)((const long long*)si)[tid] : ((const int*)si)[tid];
        g_need_out[n] = 1;
    } else if (tid < 2 * BATCH) {
        int i = tid - BATCH;
        int n = is64 ? (int)((const long long*)di)[i] : ((const int*)di)[i];
        g_need_out[n] = 1;
    }
}

// ---------------- 2) mark needed h rows + count gated in-edges ----------------
__global__ void mark_src_kernel(const void* __restrict__ ei) {
    int e = blockIdx.x * blockDim.x + threadIdx.x;
    if (e >= E_EDGES) return;
    int d = load_idx(ei, E_EDGES + e);
    if (g_need_out[d]) {
        int s = load_idx(ei, e);
        g_need_h[s] = 1;
        atomicAdd(&g_cnt[d], 1);
    }
}

// ---------------- 3) compact: h list, union list, out list ----------------
__global__ void compact_kernel() {
    int n = blockIdx.x * blockDim.x + threadIdx.x;
    if (n >= N_NODES) return;
    unsigned char nh = g_need_h[n];
    unsigned char no = g_need_out[n];
    if (nh) {
        int p = atomicAdd(&g_hcount, 1);
        g_hlist[p] = n;
        g_hidx[n] = p;
    }
    if (nh || no) {
        int p = atomicAdd(&g_ucount, 1);
        g_ulist[p] = n;
    }
    if (no) {
        int p = atomicAdd(&g_ocount, 1);
        g_olist[p] = n;
    }
}

// ---------------- 4) c vectors + rel logits (merged) ----------------
__global__ void cvec_rel_kernel(const float* __restrict__ Wm,
                                const float* __restrict__ a_src,
                                const float* __restrict__ a_dst,
                                const float* __restrict__ rel_feat,
                                const float* __restrict__ a_rel) {
    int gwid = (blockIdx.x * blockDim.x + threadIdx.x) >> 5;
    int lane = threadIdx.x & 31;
    if (gwid < IN_DIM * HEADS) {
        int k = gwid >> 2, h = gwid & 3;
        const float* wrow = Wm + (size_t)k * HID + h * OUT_DIM;
        const float* as = a_src + h * OUT_DIM;
        const float* ad = a_dst + h * OUT_DIM;
        float cs = 0.f, cd = 0.f;
        for (int d = lane; d < OUT_DIM; d += 32) {
            float w = wrow[d];
            cs = fmaf(w, as[d], cs);
            cd = fmaf(w, ad[d], cd);
        }
        cs = warp_reduce(cs);
        cd = warp_reduce(cd);
        if (lane == 0) { g_csrc[k * 4 + h] = cs; g_cdst[k * 4 + h] = cd; }
    } else if (gwid < IN_DIM * HEADS + NUM_REL * HEADS) {
        int w2 = gwid - IN_DIM * HEADS;
        int r = w2 >> 2, h = w2 & 3;
        const float* rp = rel_feat + (size_t)r * HID + h * OUT_DIM;
        const float* ar = a_rel + h * OUT_DIM;
        float s = 0.f;
        for (int d = lane; d < OUT_DIM; d += 32) s = fmaf(rp[d], ar[d], s);
        s = warp_reduce(s);
        if (lane == 0) g_rlog[w2] = s;
    }
}

// ---------------- 5) s-pass over union (plain stores) + W transpose ----------------
__global__ void __launch_bounds__(256) split_fused_kernel(const float* __restrict__ A,
                                                          const float* __restrict__ Wm) {
    __shared__ float sm[8][8];
    __shared__ float tile[32][33];
    const int bid = blockIdx.x;
    if (bid < SPLITA_BLOCKS) {
        const int t = threadIdx.x;
        const int lane = t & 31;
        const int warp = t >> 5;
        const int ulen = g_ucount;
        float4 cs[4], cd[4];
        #pragma unroll
        for (int q = 0; q < 4; q++) {
            cs[q] = ((const float4*)g_csrc)[t * 4 + q];
            cd[q] = ((const float4*)g_cdst)[t * 4 + q];
        }
        for (int li = bid; li < ulen; li += SPLITA_BLOCKS) {
            const int n = g_ulist[li];
            float4 a = ((const float4*)(A + (size_t)n * IN_DIM))[t];
            float av[4] = {a.x, a.y, a.z, a.w};
            float v[8] = {0.f, 0.f, 0.f, 0.f, 0.f, 0.f, 0.f, 0.f};
            #pragma unroll
            for (int q = 0; q < 4; q++) {
                v[0] = fmaf(av[q], cs[q].x, v[0]); v[1] = fmaf(av[q], cs[q].y, v[1]);
                v[2] = fmaf(av[q], cs[q].z, v[2]); v[3] = fmaf(av[q], cs[q].w, v[3]);
                v[4] = fmaf(av[q], cd[q].x, v[4]); v[5] = fmaf(av[q], cd[q].y, v[5]);
                v[6] = fmaf(av[q], cd[q].z, v[6]); v[7] = fmaf(av[q], cd[q].w, v[7]);
            }
            if (g_need_h[n]) {
                __half2* ph = (__half2*)(g_Ah + (size_t)n * IN_DIM) + t * 2;
                ph[0] = __halves2half2(__float2half(a.x), __float2half(a.y));
                ph[1] = __halves2half2(__float2half(a.z), __float2half(a.w));
            }
            #pragma unroll
            for (int o = 16; o > 0; o >>= 1)
                #pragma unroll
                for (int q = 0; q < 8; q++)
                    v[q] += __shfl_xor_sync(0xffffffffu, v[q], o);
            if (lane < 8) sm[warp][lane] = v[lane];
            __syncthreads();
            if (t < 8) {
                float acc = 0.f;
                #pragma unroll
                for (int w = 0; w < 8; w++) acc += sm[w][t];
                if (t < 4) g_ssrc[n * 4 + t] = acc;
                else       g_sdst[n * 4 + (t - 4)] = acc;
            }
            __syncthreads();
        }
    } else {
        const int b = bid - SPLITA_BLOCKS;
        const int tx = threadIdx.x & 31;
        const int ty = threadIdx.x >> 5;
        const int k0 = (b % (IN_DIM / 32)) * 32;
        const int n0 = (b / (IN_DIM / 32)) * 32;
        #pragma unroll
        for (int j = 0; j < 4; j++) {
            int k = k0 + ty + j * 8;
            int n = n0 + tx;
            tile[ty + j * 8][tx] = (n < HID) ? Wm[(size_t)k * HID + n] : 0.0f;
        }
        __syncthreads();
        #pragma unroll
        for (int j = 0; j < 4; j++) {
            int n = n0 + ty + j * 8;
            int k = k0 + tx;
            g_Bh[(size_t)n * IN_DIM + k] = __float2half(tile[tx][ty + j * 8]);
        }
    }
}

// ---------------- 6) HMMA GEMM over compacted rows (single fp16 pass) ----------------
__global__ void __launch_bounds__(256) gemm_mma_kernel() {
    __shared__ int rowlist[BM];
    const int len = g_hcount;
    const int mt0 = blockIdx.y * BM;
    if (mt0 >= len) return;

    extern __shared__ char smem[];
    const uint32_t sbase = smem_u32(smem);
    const int t = threadIdx.x;
    const int lane = t & 31;
    const int warp = t >> 5;
    const int wm = warp >> 1;
    const int wn = warp & 1;
    const int n0 = blockIdx.x * BN;

    if (t < BM) {
        int rr = mt0 + t;
        rowlist[t] = g_hlist[rr < len ? rr : len - 1];
    }
    __syncthreads();

    float acc[2][4][4];
    #pragma unroll
    for (int mi = 0; mi < 2; mi++)
        #pragma unroll
        for (int nj = 0; nj < 4; nj++)
            #pragma unroll
            for (int q = 0; q < 4; q++) acc[mi][nj][q] = 0.0f;

    auto load_chunk = [&](int c, int buf) {
        #pragma unroll
        for (int i = 0; i < 2; i++) {
            int lin = i * 256 + t;
            int r = lin >> 2, seg = lin & 3;
            int node = rowlist[r];
            size_t go = (size_t)node * IN_DIM + c * BK + seg * 8;
            uint32_t so = (uint32_t)(r * A_STRIDE + seg * 16);
            cp_async16(sbase + SA_OFF(buf) + so, g_Ah + go);
        }
        {
            int r = t >> 2, seg = t & 3;
            size_t go = (size_t)(n0 + r) * IN_DIM + c * BK + seg * 8;
            uint32_t so = (uint32_t)(r * A_STRIDE + seg * 16);
            cp_async16(sbase + SB_OFF(buf) + so, g_Bh + go);
        }
        cp_commit();
    };

    load_chunk(0, 0);
    load_chunk(1, 1);

    for (int c = 0; c < NCHUNK; c++) {
        if (c == NCHUNK - 1) cp_wait<0>(); else cp_wait<1>();
        __syncthreads();
        const int buf = c & 1;

        #pragma unroll
        for (int k16 = 0; k16 < BK; k16 += 16) {
            uint32_t af[2][4];
            #pragma unroll
            for (int mi = 0; mi < 2; mi++) {
                int r = wm * 32 + mi * 16 + (lane & 7) + ((lane >> 3) & 1) * 8;
                int colB = (k16 + (lane >> 4) * 8) * 2;
                ldm_x4(af[mi], sbase + SA_OFF(buf) + r * A_STRIDE + colB);
            }
            uint32_t bf[4][2];
            #pragma unroll
            for (int pr = 0; pr < 2; pr++) {
                uint32_t r4[4];
                int n = wn * 32 + pr * 16 + ((lane >> 4) & 1) * 8 + (lane & 7);
                int colB = (k16 + ((lane >> 3) & 1) * 8) * 2;
                ldm_x4(r4, sbase + SB_OFF(buf) + n * A_STRIDE + colB);
                bf[pr * 2 + 0][0] = r4[0]; bf[pr * 2 + 0][1] = r4[1];
                bf[pr * 2 + 1][0] = r4[2]; bf[pr * 2 + 1][1] = r4[3];
            }
            #pragma unroll
            for (int mi = 0; mi < 2; mi++)
                #pragma unroll
                for (int nj = 0; nj < 4; nj++)
                    mma16816(acc[mi][nj], af[mi], bf[nj]);
        }
        __syncthreads();
        if (c + 2 < NCHUNK) load_chunk(c + 2, buf);
    }

    #pragma unroll
    for (int mi = 0; mi < 2; mi++)
        #pragma unroll
        for (int nj = 0; nj < 4; nj++) {
            int tileN = n0 + wn * 32 + nj * 8;
            if (tileN >= HID) continue;
            int col = tileN + 2 * (lane & 3);
            int lr0 = wm * 32 + mi * 16 + (lane >> 2);
            if (mt0 + lr0 < len)
                *(float2*)(g_h + (size_t)(mt0 + lr0) * HID + col) =
                    make_float2(acc[mi][nj][0], acc[mi][nj][1]);
            if (mt0 + lr0 + 8 < len)
                *(float2*)(g_h + (size_t)(mt0 + lr0 + 8) * HID + col) =
                    make_float2(acc[mi][nj][2], acc[mi][nj][3]);
        }
}

// ---------------- 7) exclusive scan ----------------
__global__ void scan_kernel() {
    __shared__ int warp_sums[32];
    __shared__ int s_base;
    const int t = threadIdx.x;
    const int lane = t & 31, wid = t >> 5;
    if (t == 0) s_base = 0;
    __syncthreads();
    const int nchunks = (N_NODES + 1023) / 1024;
    for (int ch = 0; ch < nchunks; ch++) {
        int i = ch * 1024 + t;
        int v = (i < N_NODES) ? g_cnt[i] : 0;
        int x = v;
        #pragma unroll
        for (int o = 1; o < 32; o <<= 1) {
            int y = __shfl_up_sync(0xffffffffu, x, o);
            if (lane >= o) x += y;
        }
        if (lane == 31) warp_sums[wid] = x;
        __syncthreads();
        if (wid == 0) {
            int w = warp_sums[lane];
            #pragma unroll
            for (int o = 1; o < 32; o <<= 1) {
                int y = __shfl_up_sync(0xffffffffu, w, o);
                if (lane >= o) w += y;
            }
            warp_sums[lane] = w;
        }
        __syncthreads();
        int warp_off = (wid == 0) ? 0 : warp_sums[wid - 1];
        int excl = s_base + warp_off + (x - v);
        if (i < N_NODES) { g_rowptr[i] = excl; g_cursor[i] = excl; }
        __syncthreads();
        if (t == 0) s_base += warp_sums[31];
        __syncthreads();
    }
    if (t == 0) g_rowptr[N_NODES] = s_base;
}

// ---------------- 8) CSR fill (gated) ----------------
__global__ void fill_kernel(const void* __restrict__ ei) {
    int e = blockIdx.x * blockDim.x + threadIdx.x;
    if (e >= E_EDGES) return;
    int d = load_idx(ei, E_EDGES + e);
    if (!g_need_out[d]) return;
    int pos = atomicAdd(&g_cursor[d], 1);
    g_csre[pos] = e;
}

// ---------------- 9) fused softmax + aggregate (single edge pass) ----------------
// out[n,h,:] = (sum_e ev_eh * h[s]) / (sum_e ev_eh) — normalization commutes.
__global__ void __launch_bounds__(256) agg_kernel(const void* __restrict__ ei,
                                                  const void* __restrict__ et) {
    int o    = (blockIdx.x * blockDim.x + threadIdx.x) >> 5;
    int lane = threadIdx.x & 31;
    if (o >= g_ocount) return;
    int n = g_olist[o];
    int rp0 = g_rowptr[n], rp1 = g_rowptr[n + 1];

    float4 acc[7];
    #pragma unroll
    for (int it = 0; it < 7; it++) acc[it] = make_float4(0.f, 0.f, 0.f, 0.f);
    float dn0 = 0.f, dn1 = 0.f, dn2 = 0.f, dn3 = 0.f;

    for (int j = rp0; j < rp1; j++) {
        int e = g_csre[j];
        int s = load_idx(ei, e);
        float ev_l = 0.f;
        if (lane < 4) {
            int r = load_idx(et, e);
            float x = g_ssrc[s * 4 + lane] + g_sdst[n * 4 + lane] + g_rlog[r * 4 + lane];
            x = (x >= 0.f) ? x : NEG_SLOPE * x;
            ev_l = expf(x);
        }
        float e0 = __shfl_sync(0xffffffffu, ev_l, 0);
        float e1 = __shfl_sync(0xffffffffu, ev_l, 1);
        float e2 = __shfl_sync(0xffffffffu, ev_l, 2);
        float e3 = __shfl_sync(0xffffffffu, ev_l, 3);
        dn0 += e0; dn1 += e1; dn2 += e2; dn3 += e3;
        int hrow = g_hidx[s];
        const float4* hs = (const float4*)(g_h + (size_t)hrow * HID);
        #pragma unroll
        for (int it = 0; it < 7; it++) {
            int c = lane + it * 32;
            if (c < HID / 4) {
                float a = (c < 50) ? e0 : (c < 100) ? e1 : (c < 150) ? e2 : e3;
                float4 v = hs[c];
                acc[it].x = fmaf(a, v.x, acc[it].x);
                acc[it].y = fmaf(a, v.y, acc[it].y);
                acc[it].z = fmaf(a, v.z, acc[it].z);
                acc[it].w = fmaf(a, v.w, acc[it].w);
            }
        }
    }
    float r0 = (dn0 > 0.f) ? 1.0f / dn0 : 0.0f;
    float r1 = (dn1 > 0.f) ? 1.0f / dn1 : 0.0f;
    float r2 = (dn2 > 0.f) ? 1.0f / dn2 : 0.0f;
    float r3 = (dn3 > 0.f) ? 1.0f / dn3 : 0.0f;
    float4* op = (float4*)(g_out + (size_t)n * HID);
    #pragma unroll
    for (int it = 0; it < 7; it++) {
        int c = lane + it * 32;
        if (c < HID / 4) {
            float r = (c < 50) ? r0 : (c < 100) ? r1 : (c < 150) ? r2 : r3;
            float4 v = acc[it];
            op[c] = make_float4(v.x * r, v.y * r, v.z * r, v.w * r);
        }
    }
}

// ---------------- 10) DistMult ----------------
__global__ void distmult_kernel(const float* __restrict__ bias,
                                const float* __restrict__ rel_emb,
                                const void* __restrict__ si,
                                const void* __restrict__ ri,
                                const void* __restrict__ di,
                                float* __restrict__ out) {
    int wid  = (blockIdx.x * blockDim.x + threadIdx.x) >> 5;
    int lane = threadIdx.x & 31;
    if (wid >= BATCH) return;
    int s = load_idx(si, wid);
    int r = load_idx(ri, wid);
    int d = load_idx(di, wid);
    const float* ps = g_out + (size_t)s * HID;
    const float* pd = g_out + (size_t)d * HID;
    const float* pr = rel_emb + (size_t)r * HID;
    float acc = 0.f;
    for (int k = lane; k < HID; k += 32) {
        float b = bias[k];
        acc = fmaf((ps[k] + b) * pr[k], (pd[k] + b), acc);
    }
    acc = warp_reduce(acc);
    if (lane == 0) out[wid] = acc;
}

// ---------------- launch ----------------
extern "C" void kernel_launch(void* const* d_in, const int* in_sizes, int n_in,
                              void* d_out, int out_size) {
    const float* node_emb   = (const float*)d_in[0];
    const float* Wm         = (const float*)d_in[1];
    const float* bias       = (const float*)d_in[2];
    const float* a_src      = (const float*)d_in[3];
    const float* a_dst      = (const float*)d_in[4];
    const float* a_rel      = (const float*)d_in[5];
    const float* rel_feat   = (const float*)d_in[6];
    const float* rel_emb    = (const float*)d_in[7];
    const void*  edge_index = d_in[8];
    const void*  edge_type  = d_in[9];
    const void*  src_ids    = d_in[10];
    const void*  rel_ids    = d_in[11];
    const void*  dst_ids    = d_in[12];
    float* out = (float*)d_out;

    cudaFuncSetAttribute(gemm_mma_kernel,
                         cudaFuncAttributeMaxDynamicSharedMemorySize, SM_TOT);

    init_mark_kernel<<<(N_NODES + 255) / 256, 256>>>(src_ids, dst_ids);
    mark_src_kernel<<<(E_EDGES + 255) / 256, 256>>>(edge_index);
    compact_kernel<<<(N_NODES + 255) / 256, 256>>>();
    cvec_rel_kernel<<<((IN_DIM * HEADS + NUM_REL * HEADS) * 32 + 255) / 256, 256>>>(
        Wm, a_src, a_dst, rel_feat, a_rel);
    split_fused_kernel<<<SPLITA_BLOCKS + SPLITB_BLOCKS, 256>>>(node_emb, Wm);

    dim3 ggrid(NT_N, NT_M);
    gemm_mma_kernel<<<ggrid, 256, SM_TOT>>>();

    scan_kernel<<<1, 1024>>>();
    fill_kernel<<<(E_EDGES + 255) / 256, 256>>>(edge_index);
    agg_kernel<<<(MAX_OUT * 32 + 255) / 256, 256>>>(edge_index, edge_type);
    distmult_kernel<<<(BATCH * 32 + 255) / 256, 256>>>(bias, rel_emb,
                                                       src_ids, rel_ids, dst_ids, out);
}

// round 12
// speedup vs baseline: 1.0560x; 1.0560x over previous
#include <cuda_runtime.h>
#include <cuda_fp16.h>
#include <cfloat>
#include <cstdint>

#define N_NODES 50000
#define IN_DIM  1024
#define E_EDGES 100000
#define NUM_REL 40
#define HEADS   4
#define OUT_DIM 200
#define HID     800
#define BATCH   8192
#define NEG_SLOPE 0.2f

#define BM 128
#define BN 64
#define BK 32
#define NCHUNK (IN_DIM / BK)            // 32
#define NT_M ((N_NODES + BM - 1) / BM)  // 391 (max; CTAs early-exit past len)
#define NT_N 13
#define PAD_N (NT_N * BN)               // 832

#define A_STRIDE 80
#define A_VER_SZ (128 * A_STRIDE)
#define B_VER_SZ (64 * A_STRIDE)
#define SA_OFF(buf) ((buf) * A_VER_SZ)
#define SB_OFF(buf) (2 * A_VER_SZ + (buf) * B_VER_SZ)
#define SM_TOT (2 * A_VER_SZ + 2 * B_VER_SZ)   // 30720

#define SPLITA_BLOCKS 592
#define SPLITB_BLOCKS ((IN_DIM / 32) * (PAD_N / 32))
#define MAX_OUT (2 * BATCH)             // 16384

// ---------------- scratch (device globals) ----------------
__device__ __align__(16) float g_h  [(size_t)N_NODES * HID];   // compacted h rows
__device__ __align__(16) float g_out[(size_t)N_NODES * HID];   // node-indexed
__device__ __align__(16) __half g_Ah[(size_t)N_NODES * IN_DIM];
__device__ __align__(16) __half g_Bh[(size_t)PAD_N * IN_DIM];
__device__ __align__(16) float g_csrc[IN_DIM * HEADS];
__device__ __align__(16) float g_cdst[IN_DIM * HEADS];
__device__ __align__(16) float g_ssrc  [N_NODES * HEADS];
__device__ __align__(16) float g_sdst  [N_NODES * HEADS];
__device__ float g_rlog  [NUM_REL * HEADS];
__device__ int   g_cnt   [N_NODES];
__device__ int   g_rowptr[N_NODES + 1];
__device__ int   g_cursor[N_NODES];
__device__ int   g_csre  [E_EDGES];
__device__ unsigned char g_need_out[N_NODES];   // monotone marks (deterministic per input)
__device__ unsigned char g_need_h  [N_NODES];
__device__ int   g_hidx  [N_NODES];
__device__ int   g_hlist [N_NODES];
__device__ int   g_ulist [N_NODES];
__device__ int   g_olist [MAX_OUT];
__device__ int   g_hcount;
__device__ int   g_ucount;
__device__ int   g_ocount;
__device__ int   g_is64;

// ---------------- helpers ----------------
__device__ __forceinline__ int load_idx(const void* p, int i) {
    if (g_is64) return (int)((const long long*)p)[i];
    return ((const int*)p)[i];
}
__device__ __forceinline__ float warp_reduce(float v) {
    #pragma unroll
    for (int o = 16; o > 0; o >>= 1) v += __shfl_down_sync(0xffffffffu, v, o);
    return v;
}
__device__ __forceinline__ uint32_t smem_u32(const void* p) {
    uint32_t a;
    asm("{ .reg .u64 t; cvta.to.shared.u64 t, %1; cvt.u32.u64 %0, t; }" : "=r"(a) : "l"(p));
    return a;
}
__device__ __forceinline__ void cp_async16(uint32_t s, const void* g) {
    asm volatile("cp.async.cg.shared.global [%0], [%1], 16;" :: "r"(s), "l"(g));
}
__device__ __forceinline__ void cp_commit() {
    asm volatile("cp.async.commit_group;" ::: "memory");
}
template<int NN> __device__ __forceinline__ void cp_wait() {
    asm volatile("cp.async.wait_group %0;" :: "n"(NN) : "memory");
}
__device__ __forceinline__ void ldm_x4(uint32_t* r, uint32_t addr) {
    asm volatile("ldmatrix.sync.aligned.m8n8.x4.shared.b16 {%0,%1,%2,%3}, [%4];"
                 : "=r"(r[0]), "=r"(r[1]), "=r"(r[2]), "=r"(r[3]) : "r"(addr));
}
__device__ __forceinline__ void mma16816(float* d, const uint32_t* a, const uint32_t* b) {
    asm volatile(
        "mma.sync.aligned.m16n8k16.row.col.f32.f16.f16.f32 "
        "{%0,%1,%2,%3}, {%4,%5,%6,%7}, {%8,%9}, {%0,%1,%2,%3};"
        : "+f"(d[0]), "+f"(d[1]), "+f"(d[2]), "+f"(d[3])
        : "r"(a[0]), "r"(a[1]), "r"(a[2]), "r"(a[3]), "r"(b[0]), "r"(b[1]));
}

// ---------------- 1) init + dtype detect + mark distmult endpoints ----------------
// Grid covers N_NODES*HEADS threads for s-zeroing.
__global__ void init_mark_kernel(const void* __restrict__ si, const void* __restrict__ di) {
    __shared__ int s_is64;
    const int t = threadIdx.x;
    const int tid = blockIdx.x * blockDim.x + t;
    if (t == 0) {
        const long long* p = (const long long*)si;
        int ok = 1;
        for (int i = 0; i < 64; i++) {
            long long v = p[i];
            if (v < 0 || v >= N_NODES) { ok = 0; break; }
        }
        s_is64 = ok;
        if (blockIdx.x == 0) g_is64 = ok;
    }
    if (tid < N_NODES * HEADS) { g_ssrc[tid] = 0.0f; g_sdst[tid] = 0.0f; }
    if (tid < N_NODES) g_cnt[tid] = 0;
    if (tid == 0) { g_hcount = 0; g_ucount = 0; g_ocount = 0; }
    __syncthreads();
    const int is64 = s_is64;
    if (tid < BATCH) {
        int n = is64 ? (int)((const long long*)si)[tid] : ((const int*)si)[tid];
        g_need_out[n] = 1;
    } else if (tid < 2 * BATCH) {
        int i = tid - BATCH;
        int n = is64 ? (int)((const long long*)di)[i] : ((const int*)di)[i];
        g_need_out[n] = 1;
    }
}

// ---------------- 2) mark needed h rows + count gated in-edges ----------------
__global__ void mark_src_kernel(const void* __restrict__ ei) {
    int e = blockIdx.x * blockDim.x + threadIdx.x;
    if (e >= E_EDGES) return;
    int d = load_idx(ei, E_EDGES + e);
    if (g_need_out[d]) {
        int s = load_idx(ei, e);
        g_need_h[s] = 1;
        atomicAdd(&g_cnt[d], 1);
    }
}

// ---------------- 3) compact: h list, union list, out list ----------------
__global__ void compact_kernel() {
    int n = blockIdx.x * blockDim.x + threadIdx.x;
    if (n >= N_NODES) return;
    unsigned char nh = g_need_h[n];
    unsigned char no = g_need_out[n];
    if (nh) {
        int p = atomicAdd(&g_hcount, 1);
        g_hlist[p] = n;
        g_hidx[n] = p;
    }
    if (nh || no) {
        int p = atomicAdd(&g_ucount, 1);
        g_ulist[p] = n;
    }
    if (no) {
        int p = atomicAdd(&g_ocount, 1);
        g_olist[p] = n;
    }
}

// ---------------- 4) c vectors + rel logits (merged) ----------------
__global__ void cvec_rel_kernel(const float* __restrict__ Wm,
                                const float* __restrict__ a_src,
                                const float* __restrict__ a_dst,
                                const float* __restrict__ rel_feat,
                                const float* __restrict__ a_rel) {
    int gwid = (blockIdx.x * blockDim.x + threadIdx.x) >> 5;
    int lane = threadIdx.x & 31;
    if (gwid < IN_DIM * HEADS) {
        int k = gwid >> 2, h = gwid & 3;
        const float* wrow = Wm + (size_t)k * HID + h * OUT_DIM;
        const float* as = a_src + h * OUT_DIM;
        const float* ad = a_dst + h * OUT_DIM;
        float cs = 0.f, cd = 0.f;
        for (int d = lane; d < OUT_DIM; d += 32) {
            float w = wrow[d];
            cs = fmaf(w, as[d], cs);
            cd = fmaf(w, ad[d], cd);
        }
        cs = warp_reduce(cs);
        cd = warp_reduce(cd);
        if (lane == 0) { g_csrc[k * 4 + h] = cs; g_cdst[k * 4 + h] = cd; }
    } else if (gwid < IN_DIM * HEADS + NUM_REL * HEADS) {
        int w2 = gwid - IN_DIM * HEADS;
        int r = w2 >> 2, h = w2 & 3;
        const float* rp = rel_feat + (size_t)r * HID + h * OUT_DIM;
        const float* ar = a_rel + h * OUT_DIM;
        float s = 0.f;
        for (int d = lane; d < OUT_DIM; d += 32) s = fmaf(rp[d], ar[d], s);
        s = warp_reduce(s);
        if (lane == 0) g_rlog[w2] = s;
    }
}

// ---------------- 5) s-pass over union (R10-style: butterfly + atomics) + W^T ------
__global__ void __launch_bounds__(256) split_fused_kernel(const float* __restrict__ A,
                                                          const float* __restrict__ Wm) {
    const int bid = blockIdx.x;
    if (bid < SPLITA_BLOCKS) {
        const int t = threadIdx.x;
        const int lane = t & 31;
        const int ulen = g_ucount;
        float4 cs[4], cd[4];
        #pragma unroll
        for (int q = 0; q < 4; q++) {
            cs[q] = ((const float4*)g_csrc)[t * 4 + q];
            cd[q] = ((const float4*)g_cdst)[t * 4 + q];
        }
        for (int li = bid; li < ulen; li += SPLITA_BLOCKS) {
            const int n = g_ulist[li];
            float4 a = ((const float4*)(A + (size_t)n * IN_DIM))[t];
            float av[4] = {a.x, a.y, a.z, a.w};
            float ss0 = 0.f, ss1 = 0.f, ss2 = 0.f, ss3 = 0.f;
            float sd0 = 0.f, sd1 = 0.f, sd2 = 0.f, sd3 = 0.f;
            #pragma unroll
            for (int q = 0; q < 4; q++) {
                ss0 = fmaf(av[q], cs[q].x, ss0); ss1 = fmaf(av[q], cs[q].y, ss1);
                ss2 = fmaf(av[q], cs[q].z, ss2); ss3 = fmaf(av[q], cs[q].w, ss3);
                sd0 = fmaf(av[q], cd[q].x, sd0); sd1 = fmaf(av[q], cd[q].y, sd1);
                sd2 = fmaf(av[q], cd[q].z, sd2); sd3 = fmaf(av[q], cd[q].w, sd3);
            }
            if (g_need_h[n]) {
                __half2* ph = (__half2*)(g_Ah + (size_t)n * IN_DIM) + t * 2;
                ph[0] = __halves2half2(__float2half(a.x), __float2half(a.y));
                ph[1] = __halves2half2(__float2half(a.z), __float2half(a.w));
            }
            #pragma unroll
            for (int o = 16; o > 0; o >>= 1) {
                ss0 += __shfl_xor_sync(0xffffffffu, ss0, o);
                ss1 += __shfl_xor_sync(0xffffffffu, ss1, o);
                ss2 += __shfl_xor_sync(0xffffffffu, ss2, o);
                ss3 += __shfl_xor_sync(0xffffffffu, ss3, o);
                sd0 += __shfl_xor_sync(0xffffffffu, sd0, o);
                sd1 += __shfl_xor_sync(0xffffffffu, sd1, o);
                sd2 += __shfl_xor_sync(0xffffffffu, sd2, o);
                sd3 += __shfl_xor_sync(0xffffffffu, sd3, o);
            }
            if (lane == 0) {
                atomicAdd(&g_ssrc[n * 4 + 0], ss0);
                atomicAdd(&g_ssrc[n * 4 + 1], ss1);
                atomicAdd(&g_ssrc[n * 4 + 2], ss2);
                atomicAdd(&g_ssrc[n * 4 + 3], ss3);
                atomicAdd(&g_sdst[n * 4 + 0], sd0);
                atomicAdd(&g_sdst[n * 4 + 1], sd1);
                atomicAdd(&g_sdst[n * 4 + 2], sd2);
                atomicAdd(&g_sdst[n * 4 + 3], sd3);
            }
        }
    } else {
        __shared__ float tile[32][33];
        const int b = bid - SPLITA_BLOCKS;
        const int tx = threadIdx.x & 31;
        const int ty = threadIdx.x >> 5;
        const int k0 = (b % (IN_DIM / 32)) * 32;
        const int n0 = (b / (IN_DIM / 32)) * 32;
        #pragma unroll
        for (int j = 0; j < 4; j++) {
            int k = k0 + ty + j * 8;
            int n = n0 + tx;
            tile[ty + j * 8][tx] = (n < HID) ? Wm[(size_t)k * HID + n] : 0.0f;
        }
        __syncthreads();
        #pragma unroll
        for (int j = 0; j < 4; j++) {
            int n = n0 + ty + j * 8;
            int k = k0 + tx;
            g_Bh[(size_t)n * IN_DIM + k] = __float2half(tile[tx][ty + j * 8]);
        }
    }
}

// ---------------- 6) HMMA GEMM over compacted rows (single fp16 pass) ----------------
__global__ void __launch_bounds__(256) gemm_mma_kernel() {
    __shared__ int rowlist[BM];
    const int len = g_hcount;
    const int mt0 = blockIdx.y * BM;
    if (mt0 >= len) return;

    extern __shared__ char smem[];
    const uint32_t sbase = smem_u32(smem);
    const int t = threadIdx.x;
    const int lane = t & 31;
    const int warp = t >> 5;
    const int wm = warp >> 1;
    const int wn = warp & 1;
    const int n0 = blockIdx.x * BN;

    if (t < BM) {
        int rr = mt0 + t;
        rowlist[t] = g_hlist[rr < len ? rr : len - 1];
    }
    __syncthreads();

    float acc[2][4][4];
    #pragma unroll
    for (int mi = 0; mi < 2; mi++)
        #pragma unroll
        for (int nj = 0; nj < 4; nj++)
            #pragma unroll
            for (int q = 0; q < 4; q++) acc[mi][nj][q] = 0.0f;

    auto load_chunk = [&](int c, int buf) {
        #pragma unroll
        for (int i = 0; i < 2; i++) {
            int lin = i * 256 + t;
            int r = lin >> 2, seg = lin & 3;
            int node = rowlist[r];
            size_t go = (size_t)node * IN_DIM + c * BK + seg * 8;
            uint32_t so = (uint32_t)(r * A_STRIDE + seg * 16);
            cp_async16(sbase + SA_OFF(buf) + so, g_Ah + go);
        }
        {
            int r = t >> 2, seg = t & 3;
            size_t go = (size_t)(n0 + r) * IN_DIM + c * BK + seg * 8;
            uint32_t so = (uint32_t)(r * A_STRIDE + seg * 16);
            cp_async16(sbase + SB_OFF(buf) + so, g_Bh + go);
        }
        cp_commit();
    };

    load_chunk(0, 0);
    load_chunk(1, 1);

    for (int c = 0; c < NCHUNK; c++) {
        if (c == NCHUNK - 1) cp_wait<0>(); else cp_wait<1>();
        __syncthreads();
        const int buf = c & 1;

        #pragma unroll
        for (int k16 = 0; k16 < BK; k16 += 16) {
            uint32_t af[2][4];
            #pragma unroll
            for (int mi = 0; mi < 2; mi++) {
                int r = wm * 32 + mi * 16 + (lane & 7) + ((lane >> 3) & 1) * 8;
                int colB = (k16 + (lane >> 4) * 8) * 2;
                ldm_x4(af[mi], sbase + SA_OFF(buf) + r * A_STRIDE + colB);
            }
            uint32_t bf[4][2];
            #pragma unroll
            for (int pr = 0; pr < 2; pr++) {
                uint32_t r4[4];
                int n = wn * 32 + pr * 16 + ((lane >> 4) & 1) * 8 + (lane & 7);
                int colB = (k16 + ((lane >> 3) & 1) * 8) * 2;
                ldm_x4(r4, sbase + SB_OFF(buf) + n * A_STRIDE + colB);
                bf[pr * 2 + 0][0] = r4[0]; bf[pr * 2 + 0][1] = r4[1];
                bf[pr * 2 + 1][0] = r4[2]; bf[pr * 2 + 1][1] = r4[3];
            }
            #pragma unroll
            for (int mi = 0; mi < 2; mi++)
                #pragma unroll
                for (int nj = 0; nj < 4; nj++)
                    mma16816(acc[mi][nj], af[mi], bf[nj]);
        }
        __syncthreads();
        if (c + 2 < NCHUNK) load_chunk(c + 2, buf);
    }

    #pragma unroll
    for (int mi = 0; mi < 2; mi++)
        #pragma unroll
        for (int nj = 0; nj < 4; nj++) {
            int tileN = n0 + wn * 32 + nj * 8;
            if (tileN >= HID) continue;
            int col = tileN + 2 * (lane & 3);
            int lr0 = wm * 32 + mi * 16 + (lane >> 2);
            if (mt0 + lr0 < len)
                *(float2*)(g_h + (size_t)(mt0 + lr0) * HID + col) =
                    make_float2(acc[mi][nj][0], acc[mi][nj][1]);
            if (mt0 + lr0 + 8 < len)
                *(float2*)(g_h + (size_t)(mt0 + lr0 + 8) * HID + col) =
                    make_float2(acc[mi][nj][2], acc[mi][nj][3]);
        }
}

// ---------------- 7) exclusive scan ----------------
__global__ void scan_kernel() {
    __shared__ int warp_sums[32];
    __shared__ int s_base;
    const int t = threadIdx.x;
    const int lane = t & 31, wid = t >> 5;
    if (t == 0) s_base = 0;
    __syncthreads();
    const int nchunks = (N_NODES + 1023) / 1024;
    for (int ch = 0; ch < nchunks; ch++) {
        int i = ch * 1024 + t;
        int v = (i < N_NODES) ? g_cnt[i] : 0;
        int x = v;
        #pragma unroll
        for (int o = 1; o < 32; o <<= 1) {
            int y = __shfl_up_sync(0xffffffffu, x, o);
            if (lane >= o) x += y;
        }
        if (lane == 31) warp_sums[wid] = x;
        __syncthreads();
        if (wid == 0) {
            int w = warp_sums[lane];
            #pragma unroll
            for (int o = 1; o < 32; o <<= 1) {
                int y = __shfl_up_sync(0xffffffffu, w, o);
                if (lane >= o) w += y;
            }
            warp_sums[lane] = w;
        }
        __syncthreads();
        int warp_off = (wid == 0) ? 0 : warp_sums[wid - 1];
        int excl = s_base + warp_off + (x - v);
        if (i < N_NODES) { g_rowptr[i] = excl; g_cursor[i] = excl; }
        __syncthreads();
        if (t == 0) s_base += warp_sums[31];
        __syncthreads();
    }
    if (t == 0) g_rowptr[N_NODES] = s_base;
}

// ---------------- 8) CSR fill (gated) ----------------
__global__ void fill_kernel(const void* __restrict__ ei) {
    int e = blockIdx.x * blockDim.x + threadIdx.x;
    if (e >= E_EDGES) return;
    int d = load_idx(ei, E_EDGES + e);
    if (!g_need_out[d]) return;
    int pos = atomicAdd(&g_cursor[d], 1);
    g_csre[pos] = e;
}

// ---------------- 9) fused softmax + aggregate (single edge pass) ----------------
__global__ void __launch_bounds__(256) agg_kernel(const void* __restrict__ ei,
                                                  const void* __restrict__ et) {
    int o    = (blockIdx.x * blockDim.x + threadIdx.x) >> 5;
    int lane = threadIdx.x & 31;
    if (o >= g_ocount) return;
    int n = g_olist[o];
    int rp0 = g_rowptr[n], rp1 = g_rowptr[n + 1];

    float4 acc[7];
    #pragma unroll
    for (int it = 0; it < 7; it++) acc[it] = make_float4(0.f, 0.f, 0.f, 0.f);
    float dn0 = 0.f, dn1 = 0.f, dn2 = 0.f, dn3 = 0.f;

    for (int j = rp0; j < rp1; j++) {
        int e = g_csre[j];
        int s = load_idx(ei, e);
        float ev_l = 0.f;
        if (lane < 4) {
            int r = load_idx(et, e);
            float x = g_ssrc[s * 4 + lane] + g_sdst[n * 4 + lane] + g_rlog[r * 4 + lane];
            x = (x >= 0.f) ? x : NEG_SLOPE * x;
            ev_l = expf(x);
        }
        float e0 = __shfl_sync(0xffffffffu, ev_l, 0);
        float e1 = __shfl_sync(0xffffffffu, ev_l, 1);
        float e2 = __shfl_sync(0xffffffffu, ev_l, 2);
        float e3 = __shfl_sync(0xffffffffu, ev_l, 3);
        dn0 += e0; dn1 += e1; dn2 += e2; dn3 += e3;
        int hrow = g_hidx[s];
        const float4* hs = (const float4*)(g_h + (size_t)hrow * HID);
        #pragma unroll
        for (int it = 0; it < 7; it++) {
            int c = lane + it * 32;
            if (c < HID / 4) {
                float a = (c < 50) ? e0 : (c < 100) ? e1 : (c < 150) ? e2 : e3;
                float4 v = hs[c];
                acc[it].x = fmaf(a, v.x, acc[it].x);
                acc[it].y = fmaf(a, v.y, acc[it].y);
                acc[it].z = fmaf(a, v.z, acc[it].z);
                acc[it].w = fmaf(a, v.w, acc[it].w);
            }
        }
    }
    float r0 = (dn0 > 0.f) ? 1.0f / dn0 : 0.0f;
    float r1 = (dn1 > 0.f) ? 1.0f / dn1 : 0.0f;
    float r2 = (dn2 > 0.f) ? 1.0f / dn2 : 0.0f;
    float r3 = (dn3 > 0.f) ? 1.0f / dn3 : 0.0f;
    float4* op = (float4*)(g_out + (size_t)n * HID);
    #pragma unroll
    for (int it = 0; it < 7; it++) {
        int c = lane + it * 32;
        if (c < HID / 4) {
            float r = (c < 50) ? r0 : (c < 100) ? r1 : (c < 150) ? r2 : r3;
            float4 v = acc[it];
            op[c] = make_float4(v.x * r, v.y * r, v.z * r, v.w * r);
        }
    }
}

// ---------------- 10) DistMult ----------------
__global__ void distmult_kernel(const float* __restrict__ bias,
                                const float* __restrict__ rel_emb,
                                const void* __restrict__ si,
                                const void* __restrict__ ri,
                                const void* __restrict__ di,
                                float* __restrict__ out) {
    int wid  = (blockIdx.x * blockDim.x + threadIdx.x) >> 5;
    int lane = threadIdx.x & 31;
    if (wid >= BATCH) return;
    int s = load_idx(si, wid);
    int r = load_idx(ri, wid);
    int d = load_idx(di, wid);
    const float* ps = g_out + (size_t)s * HID;
    const float* pd = g_out + (size_t)d * HID;
    const float* pr = rel_emb + (size_t)r * HID;
    float acc = 0.f;
    for (int k = lane; k < HID; k += 32) {
        float b = bias[k];
        acc = fmaf((ps[k] + b) * pr[k], (pd[k] + b), acc);
    }
    acc = warp_reduce(acc);
    if (lane == 0) out[wid] = acc;
}

// ---------------- launch ----------------
extern "C" void kernel_launch(void* const* d_in, const int* in_sizes, int n_in,
                              void* d_out, int out_size) {
    const float* node_emb   = (const float*)d_in[0];
    const float* Wm         = (const float*)d_in[1];
    const float* bias       = (const float*)d_in[2];
    const float* a_src      = (const float*)d_in[3];
    const float* a_dst      = (const float*)d_in[4];
    const float* a_rel      = (const float*)d_in[5];
    const float* rel_feat   = (const float*)d_in[6];
    const float* rel_emb    = (const float*)d_in[7];
    const void*  edge_index = d_in[8];
    const void*  edge_type  = d_in[9];
    const void*  src_ids    = d_in[10];
    const void*  rel_ids    = d_in[11];
    const void*  dst_ids    = d_in[12];
    float* out = (float*)d_out;

    cudaFuncSetAttribute(gemm_mma_kernel,
                         cudaFuncAttributeMaxDynamicSharedMemorySize, SM_TOT);

    init_mark_kernel<<<(N_NODES * HEADS + 255) / 256, 256>>>(src_ids, dst_ids);
    mark_src_kernel<<<(E_EDGES + 255) / 256, 256>>>(edge_index);
    compact_kernel<<<(N_NODES + 255) / 256, 256>>>();
    cvec_rel_kernel<<<((IN_DIM * HEADS + NUM_REL * HEADS) * 32 + 255) / 256, 256>>>(
        Wm, a_src, a_dst, rel_feat, a_rel);
    split_fused_kernel<<<SPLITA_BLOCKS + SPLITB_BLOCKS, 256>>>(node_emb, Wm);

    dim3 ggrid(NT_N, NT_M);
    gemm_mma_kernel<<<ggrid, 256, SM_TOT>>>();

    scan_kernel<<<1, 1024>>>();
    fill_kernel<<<(E_EDGES + 255) / 256, 256>>>(edge_index);
    agg_kernel<<<(MAX_OUT * 32 + 255) / 256, 256>>>(edge_index, edge_type);
    distmult_kernel<<<(BATCH * 32 + 255) / 256, 256>>>(bias, rel_emb,
                                                       src_ids, rel_ids, dst_ids, out);
}

// round 13
// speedup vs baseline: 1.0622x; 1.0058x over previous
#include <cuda_runtime.h>
#include <cuda_fp16.h>
#include <cfloat>
#include <cstdint>

#define N_NODES 50000
#define IN_DIM  1024
#define E_EDGES 100000
#define NUM_REL 40
#define HEADS   4
#define OUT_DIM 200
#define HID     800
#define BATCH   8192
#define NEG_SLOPE 0.2f

#define BM 128
#define BN 128
#define BK 32
#define NCHUNK (IN_DIM / BK)            // 32
#define NT_M ((N_NODES + BM - 1) / BM)  // 391 (max; CTAs early-exit past len)
#define NT_N 7                          // ceil(800/128)
#define PAD_N (NT_N * BN)               // 896

#define A_STRIDE 80
#define A_VER_SZ (128 * A_STRIDE)       // 10240
#define B_VER_SZ (128 * A_STRIDE)       // 10240
#define SA_OFF(buf) ((buf) * A_VER_SZ)
#define SB_OFF(buf) (2 * A_VER_SZ + (buf) * B_VER_SZ)
#define SM_TOT (2 * A_VER_SZ + 2 * B_VER_SZ)   // 40960

#define SPLITA_BLOCKS 592
#define SPLITB_BLOCKS ((IN_DIM / 32) * (PAD_N / 32))   // 32*28 = 896
#define MAX_OUT (2 * BATCH)             // 16384

// ---------------- scratch (device globals) ----------------
__device__ __align__(16) float g_h  [(size_t)N_NODES * HID];   // compacted h rows
__device__ __align__(16) float g_out[(size_t)N_NODES * HID];   // node-indexed
__device__ __align__(16) __half g_Ah[(size_t)N_NODES * IN_DIM];
__device__ __align__(16) __half g_Bh[(size_t)PAD_N * IN_DIM];
__device__ __align__(16) float g_csrc[IN_DIM * HEADS];
__device__ __align__(16) float g_cdst[IN_DIM * HEADS];
__device__ __align__(16) float g_ssrc  [N_NODES * HEADS];
__device__ __align__(16) float g_sdst  [N_NODES * HEADS];
__device__ float g_rlog  [NUM_REL * HEADS];
__device__ int   g_cnt   [N_NODES];
__device__ int   g_rowptr[N_NODES + 1];
__device__ int   g_cursor[N_NODES];
__device__ int   g_csre  [E_EDGES];
__device__ unsigned char g_need_out[N_NODES];   // monotone marks (deterministic per input)
__device__ unsigned char g_need_h  [N_NODES];
__device__ int   g_hidx  [N_NODES];
__device__ int   g_hlist [N_NODES];
__device__ int   g_ulist [N_NODES];
__device__ int   g_olist [MAX_OUT];
__device__ int   g_hcount;
__device__ int   g_ucount;
__device__ int   g_ocount;
__device__ int   g_is64;

// ---------------- helpers ----------------
__device__ __forceinline__ int load_idx(const void* p, int i) {
    if (g_is64) return (int)((const long long*)p)[i];
    return ((const int*)p)[i];
}
__device__ __forceinline__ float warp_reduce(float v) {
    #pragma unroll
    for (int o = 16; o > 0; o >>= 1) v += __shfl_down_sync(0xffffffffu, v, o);
    return v;
}
__device__ __forceinline__ uint32_t smem_u32(const void* p) {
    uint32_t a;
    asm("{ .reg .u64 t; cvta.to.shared.u64 t, %1; cvt.u32.u64 %0, t; }" : "=r"(a) : "l"(p));
    return a;
}
__device__ __forceinline__ void cp_async16(uint32_t s, const void* g) {
    asm volatile("cp.async.cg.shared.global [%0], [%1], 16;" :: "r"(s), "l"(g));
}
__device__ __forceinline__ void cp_commit() {
    asm volatile("cp.async.commit_group;" ::: "memory");
}
template<int NN> __device__ __forceinline__ void cp_wait() {
    asm volatile("cp.async.wait_group %0;" :: "n"(NN) : "memory");
}
__device__ __forceinline__ void ldm_x4(uint32_t* r, uint32_t addr) {
    asm volatile("ldmatrix.sync.aligned.m8n8.x4.shared.b16 {%0,%1,%2,%3}, [%4];"
                 : "=r"(r[0]), "=r"(r[1]), "=r"(r[2]), "=r"(r[3]) : "r"(addr));
}
__device__ __forceinline__ void mma16816(float* d, const uint32_t* a, const uint32_t* b) {
    asm volatile(
        "mma.sync.aligned.m16n8k16.row.col.f32.f16.f16.f32 "
        "{%0,%1,%2,%3}, {%4,%5,%6,%7}, {%8,%9}, {%0,%1,%2,%3};"
        : "+f"(d[0]), "+f"(d[1]), "+f"(d[2]), "+f"(d[3])
        : "r"(a[0]), "r"(a[1]), "r"(a[2]), "r"(a[3]), "r"(b[0]), "r"(b[1]));
}

// ---------------- 1) init + dtype detect + mark distmult endpoints ----------------
__global__ void init_mark_kernel(const void* __restrict__ si, const void* __restrict__ di) {
    __shared__ int s_is64;
    const int t = threadIdx.x;
    const int tid = blockIdx.x * blockDim.x + t;
    if (t == 0) {
        const long long* p = (const long long*)si;
        int ok = 1;
        for (int i = 0; i < 64; i++) {
            long long v = p[i];
            if (v < 0 || v >= N_NODES) { ok = 0; break; }
        }
        s_is64 = ok;
        if (blockIdx.x == 0) g_is64 = ok;
    }
    if (tid < N_NODES * HEADS) { g_ssrc[tid] = 0.0f; g_sdst[tid] = 0.0f; }
    if (tid < N_NODES) g_cnt[tid] = 0;
    if (tid == 0) { g_hcount = 0; g_ucount = 0; g_ocount = 0; }
    __syncthreads();
    const int is64 = s_is64;
    if (tid < BATCH) {
        int n = is64 ? (int)((const long long*)si)[tid] : ((const int*)si)[tid];
        g_need_out[n] = 1;
    } else if (tid < 2 * BATCH) {
        int i = tid - BATCH;
        int n = is64 ? (int)((const long long*)di)[i] : ((const int*)di)[i];
        g_need_out[n] = 1;
    }
}

// ---------------- 2) mark needed h rows + count gated in-edges ----------------
__global__ void mark_src_kernel(const void* __restrict__ ei) {
    int e = blockIdx.x * blockDim.x + threadIdx.x;
    if (e >= E_EDGES) return;
    int d = load_idx(ei, E_EDGES + e);
    if (g_need_out[d]) {
        int s = load_idx(ei, e);
        g_need_h[s] = 1;
        atomicAdd(&g_cnt[d], 1);
    }
}

// ---------------- 3) compact: h list, union list, out list ----------------
__global__ void compact_kernel() {
    int n = blockIdx.x * blockDim.x + threadIdx.x;
    if (n >= N_NODES) return;
    unsigned char nh = g_need_h[n];
    unsigned char no = g_need_out[n];
    if (nh) {
        int p = atomicAdd(&g_hcount, 1);
        g_hlist[p] = n;
        g_hidx[n] = p;
    }
    if (nh || no) {
        int p = atomicAdd(&g_ucount, 1);
        g_ulist[p] = n;
    }
    if (no) {
        int p = atomicAdd(&g_ocount, 1);
        g_olist[p] = n;
    }
}

// ---------------- 4) c vectors + rel logits (merged) ----------------
__global__ void cvec_rel_kernel(const float* __restrict__ Wm,
                                const float* __restrict__ a_src,
                                const float* __restrict__ a_dst,
                                const float* __restrict__ rel_feat,
                                const float* __restrict__ a_rel) {
    int gwid = (blockIdx.x * blockDim.x + threadIdx.x) >> 5;
    int lane = threadIdx.x & 31;
    if (gwid < IN_DIM * HEADS) {
        int k = gwid >> 2, h = gwid & 3;
        const float* wrow = Wm + (size_t)k * HID + h * OUT_DIM;
        const float* as = a_src + h * OUT_DIM;
        const float* ad = a_dst + h * OUT_DIM;
        float cs = 0.f, cd = 0.f;
        for (int d = lane; d < OUT_DIM; d += 32) {
            float w = wrow[d];
            cs = fmaf(w, as[d], cs);
            cd = fmaf(w, ad[d], cd);
        }
        cs = warp_reduce(cs);
        cd = warp_reduce(cd);
        if (lane == 0) { g_csrc[k * 4 + h] = cs; g_cdst[k * 4 + h] = cd; }
    } else if (gwid < IN_DIM * HEADS + NUM_REL * HEADS) {
        int w2 = gwid - IN_DIM * HEADS;
        int r = w2 >> 2, h = w2 & 3;
        const float* rp = rel_feat + (size_t)r * HID + h * OUT_DIM;
        const float* ar = a_rel + h * OUT_DIM;
        float s = 0.f;
        for (int d = lane; d < OUT_DIM; d += 32) s = fmaf(rp[d], ar[d], s);
        s = warp_reduce(s);
        if (lane == 0) g_rlog[w2] = s;
    }
}

// ---------------- 5) s-pass over union (butterfly + atomics) + W^T ----------------
__global__ void __launch_bounds__(256) split_fused_kernel(const float* __restrict__ A,
                                                          const float* __restrict__ Wm) {
    const int bid = blockIdx.x;
    if (bid < SPLITA_BLOCKS) {
        const int t = threadIdx.x;
        const int lane = t & 31;
        const int ulen = g_ucount;
        float4 cs[4], cd[4];
        #pragma unroll
        for (int q = 0; q < 4; q++) {
            cs[q] = ((const float4*)g_csrc)[t * 4 + q];
            cd[q] = ((const float4*)g_cdst)[t * 4 + q];
        }
        for (int li = bid; li < ulen; li += SPLITA_BLOCKS) {
            const int n = g_ulist[li];
            float4 a = ((const float4*)(A + (size_t)n * IN_DIM))[t];
            float av[4] = {a.x, a.y, a.z, a.w};
            float ss0 = 0.f, ss1 = 0.f, ss2 = 0.f, ss3 = 0.f;
            float sd0 = 0.f, sd1 = 0.f, sd2 = 0.f, sd3 = 0.f;
            #pragma unroll
            for (int q = 0; q < 4; q++) {
                ss0 = fmaf(av[q], cs[q].x, ss0); ss1 = fmaf(av[q], cs[q].y, ss1);
                ss2 = fmaf(av[q], cs[q].z, ss2); ss3 = fmaf(av[q], cs[q].w, ss3);
                sd0 = fmaf(av[q], cd[q].x, sd0); sd1 = fmaf(av[q], cd[q].y, sd1);
                sd2 = fmaf(av[q], cd[q].z, sd2); sd3 = fmaf(av[q], cd[q].w, sd3);
            }
            if (g_need_h[n]) {
                __half2* ph = (__half2*)(g_Ah + (size_t)n * IN_DIM) + t * 2;
                ph[0] = __halves2half2(__float2half(a.x), __float2half(a.y));
                ph[1] = __halves2half2(__float2half(a.z), __float2half(a.w));
            }
            #pragma unroll
            for (int o = 16; o > 0; o >>= 1) {
                ss0 += __shfl_xor_sync(0xffffffffu, ss0, o);
                ss1 += __shfl_xor_sync(0xffffffffu, ss1, o);
                ss2 += __shfl_xor_sync(0xffffffffu, ss2, o);
                ss3 += __shfl_xor_sync(0xffffffffu, ss3, o);
                sd0 += __shfl_xor_sync(0xffffffffu, sd0, o);
                sd1 += __shfl_xor_sync(0xffffffffu, sd1, o);
                sd2 += __shfl_xor_sync(0xffffffffu, sd2, o);
                sd3 += __shfl_xor_sync(0xffffffffu, sd3, o);
            }
            if (lane == 0) {
                atomicAdd(&g_ssrc[n * 4 + 0], ss0);
                atomicAdd(&g_ssrc[n * 4 + 1], ss1);
                atomicAdd(&g_ssrc[n * 4 + 2], ss2);
                atomicAdd(&g_ssrc[n * 4 + 3], ss3);
                atomicAdd(&g_sdst[n * 4 + 0], sd0);
                atomicAdd(&g_sdst[n * 4 + 1], sd1);
                atomicAdd(&g_sdst[n * 4 + 2], sd2);
                atomicAdd(&g_sdst[n * 4 + 3], sd3);
            }
        }
    } else {
        __shared__ float tile[32][33];
        const int b = bid - SPLITA_BLOCKS;
        const int tx = threadIdx.x & 31;
        const int ty = threadIdx.x >> 5;
        const int k0 = (b % (IN_DIM / 32)) * 32;
        const int n0 = (b / (IN_DIM / 32)) * 32;
        #pragma unroll
        for (int j = 0; j < 4; j++) {
            int k = k0 + ty + j * 8;
            int n = n0 + tx;
            tile[ty + j * 8][tx] = (n < HID) ? Wm[(size_t)k * HID + n] : 0.0f;
        }
        __syncthreads();
        #pragma unroll
        for (int j = 0; j < 4; j++) {
            int n = n0 + ty + j * 8;
            int k = k0 + tx;
            g_Bh[(size_t)n * IN_DIM + k] = __float2half(tile[tx][ty + j * 8]);
        }
    }
}

// ---------------- 6) HMMA GEMM: BM=128, BN=128, warp tile 32x64 ----------------
__global__ void __launch_bounds__(256) gemm_mma_kernel() {
    __shared__ int rowlist[BM];
    const int len = g_hcount;
    const int mt0 = blockIdx.y * BM;
    if (mt0 >= len) return;

    extern __shared__ char smem[];
    const uint32_t sbase = smem_u32(smem);
    const int t = threadIdx.x;
    const int lane = t & 31;
    const int warp = t >> 5;
    const int wm = warp >> 1;          // 0..3 -> 32-row slice
    const int wn = warp & 1;           // 0..1 -> 64-col slice
    const int n0 = blockIdx.x * BN;

    if (t < BM) {
        int rr = mt0 + t;
        rowlist[t] = g_hlist[rr < len ? rr : len - 1];
    }
    __syncthreads();

    float acc[2][8][4];
    #pragma unroll
    for (int mi = 0; mi < 2; mi++)
        #pragma unroll
        for (int nj = 0; nj < 8; nj++)
            #pragma unroll
            for (int q = 0; q < 4; q++) acc[mi][nj][q] = 0.0f;

    auto load_chunk = [&](int c, int buf) {
        // A: 128 rows x 32 k fp16 = 512 16B-slots
        #pragma unroll
        for (int i = 0; i < 2; i++) {
            int lin = i * 256 + t;
            int r = lin >> 2, seg = lin & 3;
            int node = rowlist[r];
            size_t go = (size_t)node * IN_DIM + c * BK + seg * 8;
            uint32_t so = (uint32_t)(r * A_STRIDE + seg * 16);
            cp_async16(sbase + SA_OFF(buf) + so, g_Ah + go);
        }
        // B: 128 rows x 32 k fp16 = 512 16B-slots
        #pragma unroll
        for (int i = 0; i < 2; i++) {
            int lin = i * 256 + t;
            int r = lin >> 2, seg = lin & 3;
            size_t go = (size_t)(n0 + r) * IN_DIM + c * BK + seg * 8;
            uint32_t so = (uint32_t)(r * A_STRIDE + seg * 16);
            cp_async16(sbase + SB_OFF(buf) + so, g_Bh + go);
        }
        cp_commit();
    };

    load_chunk(0, 0);
    load_chunk(1, 1);

    for (int c = 0; c < NCHUNK; c++) {
        if (c == NCHUNK - 1) cp_wait<0>(); else cp_wait<1>();
        __syncthreads();
        const int buf = c & 1;

        #pragma unroll
        for (int k16 = 0; k16 < BK; k16 += 16) {
            uint32_t af[2][4];
            #pragma unroll
            for (int mi = 0; mi < 2; mi++) {
                int r = wm * 32 + mi * 16 + (lane & 7) + ((lane >> 3) & 1) * 8;
                int colB = (k16 + (lane >> 4) * 8) * 2;
                ldm_x4(af[mi], sbase + SA_OFF(buf) + r * A_STRIDE + colB);
            }
            uint32_t bf[8][2];
            #pragma unroll
            for (int pr = 0; pr < 4; pr++) {
                uint32_t r4[4];
                int n = wn * 64 + pr * 16 + ((lane >> 4) & 1) * 8 + (lane & 7);
                int colB = (k16 + ((lane >> 3) & 1) * 8) * 2;
                ldm_x4(r4, sbase + SB_OFF(buf) + n * A_STRIDE + colB);
                bf[pr * 2 + 0][0] = r4[0]; bf[pr * 2 + 0][1] = r4[1];
                bf[pr * 2 + 1][0] = r4[2]; bf[pr * 2 + 1][1] = r4[3];
            }
            #pragma unroll
            for (int mi = 0; mi < 2; mi++)
                #pragma unroll
                for (int nj = 0; nj < 8; nj++)
                    mma16816(acc[mi][nj], af[mi], bf[nj]);
        }
        __syncthreads();
        if (c + 2 < NCHUNK) load_chunk(c + 2, buf);
    }

    #pragma unroll
    for (int mi = 0; mi < 2; mi++)
        #pragma unroll
        for (int nj = 0; nj < 8; nj++) {
            int tileN = n0 + wn * 64 + nj * 8;
            if (tileN >= HID) continue;
            int col = tileN + 2 * (lane & 3);
            int lr0 = wm * 32 + mi * 16 + (lane >> 2);
            if (mt0 + lr0 < len)
                *(float2*)(g_h + (size_t)(mt0 + lr0) * HID + col) =
                    make_float2(acc[mi][nj][0], acc[mi][nj][1]);
            if (mt0 + lr0 + 8 < len)
                *(float2*)(g_h + (size_t)(mt0 + lr0 + 8) * HID + col) =
                    make_float2(acc[mi][nj][2], acc[mi][nj][3]);
        }
}

// ---------------- 7) exclusive scan ----------------
__global__ void scan_kernel() {
    __shared__ int warp_sums[32];
    __shared__ int s_base;
    const int t = threadIdx.x;
    const int lane = t & 31, wid = t >> 5;
    if (t == 0) s_base = 0;
    __syncthreads();
    const int nchunks = (N_NODES + 1023) / 1024;
    for (int ch = 0; ch < nchunks; ch++) {
        int i = ch * 1024 + t;
        int v = (i < N_NODES) ? g_cnt[i] : 0;
        int x = v;
        #pragma unroll
        for (int o = 1; o < 32; o <<= 1) {
            int y = __shfl_up_sync(0xffffffffu, x, o);
            if (lane >= o) x += y;
        }
        if (lane == 31) warp_sums[wid] = x;
        __syncthreads();
        if (wid == 0) {
            int w = warp_sums[lane];
            #pragma unroll
            for (int o = 1; o < 32; o <<= 1) {
                int y = __shfl_up_sync(0xffffffffu, w, o);
                if (lane >= o) w += y;
            }
            warp_sums[lane] = w;
        }
        __syncthreads();
        int warp_off = (wid == 0) ? 0 : warp_sums[wid - 1];
        int excl = s_base + warp_off + (x - v);
        if (i < N_NODES) { g_rowptr[i] = excl; g_cursor[i] = excl; }
        __syncthreads();
        if (t == 0) s_base += warp_sums[31];
        __syncthreads();
    }
    if (t == 0) g_rowptr[N_NODES] = s_base;
}

// ---------------- 8) CSR fill (gated) ----------------
__global__ void fill_kernel(const void* __restrict__ ei) {
    int e = blockIdx.x * blockDim.x + threadIdx.x;
    if (e >= E_EDGES) return;
    int d = load_idx(ei, E_EDGES + e);
    if (!g_need_out[d]) return;
    int pos = atomicAdd(&g_cursor[d], 1);
    g_csre[pos] = e;
}

// ---------------- 9) fused softmax + aggregate (single edge pass) ----------------
__global__ void __launch_bounds__(256) agg_kernel(const void* __restrict__ ei,
                                                  const void* __restrict__ et) {
    int o    = (blockIdx.x * blockDim.x + threadIdx.x) >> 5;
    int lane = threadIdx.x & 31;
    if (o >= g_ocount) return;
    int n = g_olist[o];
    int rp0 = g_rowptr[n], rp1 = g_rowptr[n + 1];

    float4 acc[7];
    #pragma unroll
    for (int it = 0; it < 7; it++) acc[it] = make_float4(0.f, 0.f, 0.f, 0.f);
    float dn0 = 0.f, dn1 = 0.f, dn2 = 0.f, dn3 = 0.f;

    for (int j = rp0; j < rp1; j++) {
        int e = g_csre[j];
        int s = load_idx(ei, e);
        float ev_l = 0.f;
        if (lane < 4) {
            int r = load_idx(et, e);
            float x = g_ssrc[s * 4 + lane] + g_sdst[n * 4 + lane] + g_rlog[r * 4 + lane];
            x = (x >= 0.f) ? x : NEG_SLOPE * x;
            ev_l = expf(x);
        }
        float e0 = __shfl_sync(0xffffffffu, ev_l, 0);
        float e1 = __shfl_sync(0xffffffffu, ev_l, 1);
        float e2 = __shfl_sync(0xffffffffu, ev_l, 2);
        float e3 = __shfl_sync(0xffffffffu, ev_l, 3);
        dn0 += e0; dn1 += e1; dn2 += e2; dn3 += e3;
        int hrow = g_hidx[s];
        const float4* hs = (const float4*)(g_h + (size_t)hrow * HID);
        #pragma unroll
        for (int it = 0; it < 7; it++) {
            int c = lane + it * 32;
            if (c < HID / 4) {
                float a = (c < 50) ? e0 : (c < 100) ? e1 : (c < 150) ? e2 : e3;
                float4 v = hs[c];
                acc[it].x = fmaf(a, v.x, acc[it].x);
                acc[it].y = fmaf(a, v.y, acc[it].y);
                acc[it].z = fmaf(a, v.z, acc[it].z);
                acc[it].w = fmaf(a, v.w, acc[it].w);
            }
        }
    }
    float r0 = (dn0 > 0.f) ? 1.0f / dn0 : 0.0f;
    float r1 = (dn1 > 0.f) ? 1.0f / dn1 : 0.0f;
    float r2 = (dn2 > 0.f) ? 1.0f / dn2 : 0.0f;
    float r3 = (dn3 > 0.f) ? 1.0f / dn3 : 0.0f;
    float4* op = (float4*)(g_out + (size_t)n * HID);
    #pragma unroll
    for (int it = 0; it < 7; it++) {
        int c = lane + it * 32;
        if (c < HID / 4) {
            float r = (c < 50) ? r0 : (c < 100) ? r1 : (c < 150) ? r2 : r3;
            float4 v = acc[it];
            op[c] = make_float4(v.x * r, v.y * r, v.z * r, v.w * r);
        }
    }
}

// ---------------- 10) DistMult ----------------
__global__ void distmult_kernel(const float* __restrict__ bias,
                                const float* __restrict__ rel_emb,
                                const void* __restrict__ si,
                                const void* __restrict__ ri,
                                const void* __restrict__ di,
                                float* __restrict__ out) {
    int wid  = (blockIdx.x * blockDim.x + threadIdx.x) >> 5;
    int lane = threadIdx.x & 31;
    if (wid >= BATCH) return;
    int s = load_idx(si, wid);
    int r = load_idx(ri, wid);
    int d = load_idx(di, wid);
    const float* ps = g_out + (size_t)s * HID;
    const float* pd = g_out + (size_t)d * HID;
    const float* pr = rel_emb + (size_t)r * HID;
    float acc = 0.f;
    for (int k = lane; k < HID; k += 32) {
        float b = bias[k];
        acc = fmaf((ps[k] + b) * pr[k], (pd[k] + b), acc);
    }
    acc = warp_reduce(acc);
    if (lane == 0) out[wid] = acc;
}

// ---------------- launch ----------------
extern "C" void kernel_launch(void* const* d_in, const int* in_sizes, int n_in,
                              void* d_out, int out_size) {
    const float* node_emb   = (const float*)d_in[0];
    const float* Wm         = (const float*)d_in[1];
    const float* bias       = (const float*)d_in[2];
    const float* a_src      = (const float*)d_in[3];
    const float* a_dst      = (const float*)d_in[4];
    const float* a_rel      = (const float*)d_in[5];
    const float* rel_feat   = (const float*)d_in[6];
    const float* rel_emb    = (const float*)d_in[7];
    const void*  edge_index = d_in[8];
    const void*  edge_type  = d_in[9];
    const void*  src_ids    = d_in[10];
    const void*  rel_ids    = d_in[11];
    const void*  dst_ids    = d_in[12];
    float* out = (float*)d_out;

    cudaFuncSetAttribute(gemm_mma_kernel,
                         cudaFuncAttributeMaxDynamicSharedMemorySize, SM_TOT);

    init_mark_kernel<<<(N_NODES * HEADS + 255) / 256, 256>>>(src_ids, dst_ids);
    mark_src_kernel<<<(E_EDGES + 255) / 256, 256>>>(edge_index);
    compact_kernel<<<(N_NODES + 255) / 256, 256>>>();
    cvec_rel_kernel<<<((IN_DIM * HEADS + NUM_REL * HEADS) * 32 + 255) / 256, 256>>>(
        Wm, a_src, a_dst, rel_feat, a_rel);
    split_fused_kernel<<<SPLITA_BLOCKS + SPLITB_BLOCKS, 256>>>(node_emb, Wm);

    dim3 ggrid(NT_N, NT_M);
    gemm_mma_kernel<<<ggrid, 256, SM_TOT>>>();

    scan_kernel<<<1, 1024>>>();
    fill_kernel<<<(E_EDGES + 255) / 256, 256>>>(edge_index);
    agg_kernel<<<(MAX_OUT * 32 + 255) / 256, 256>>>(edge_index, edge_type);
    distmult_kernel<<<(BATCH * 32 + 255) / 256, 256>>>(bias, rel_emb,
                                                       src_ids, rel_ids, dst_ids, out);
}

// round 14
// speedup vs baseline: 1.2201x; 1.1487x over previous
#include <cuda_runtime.h>
#include <cuda_fp16.h>
#include <cfloat>
#include <cstdint>

#define N_NODES 50000
#define IN_DIM  1024
#define E_EDGES 100000
#define NUM_REL 40
#define HEADS   4
#define OUT_DIM 200
#define HID     800
#define BATCH   8192
#define NEG_SLOPE 0.2f

#define BM 128
#define BN 128
#define BK 32
#define NCHUNK (IN_DIM / BK)            // 32
#define NT_M ((N_NODES + BM - 1) / BM)
#define NT_N 7
#define PAD_N (NT_N * BN)               // 896

#define A_STRIDE 80
#define A_VER_SZ (128 * A_STRIDE)
#define B_VER_SZ (128 * A_STRIDE)
#define SA_OFF(buf) ((buf) * A_VER_SZ)
#define SB_OFF(buf) (2 * A_VER_SZ + (buf) * B_VER_SZ)
#define SM_TOT (2 * A_VER_SZ + 2 * B_VER_SZ)   // 40960

#define SPLITA_BLOCKS 592
#define SPLITB_BLOCKS ((IN_DIM / 32) * (PAD_N / 32))
#define MAX_OUT (2 * BATCH)

// ---------------- scratch (device globals) ----------------
__device__ __align__(16) __half g_h  [(size_t)N_NODES * HID];  // compacted h rows (fp16)
__device__ __align__(16) float g_out[(size_t)N_NODES * HID];   // node-indexed
__device__ __align__(16) __half g_Ah[(size_t)N_NODES * IN_DIM];
__device__ __align__(16) __half g_Bh[(size_t)PAD_N * IN_DIM];
__device__ __align__(16) float g_csrc[IN_DIM * HEADS];
__device__ __align__(16) float g_cdst[IN_DIM * HEADS];
__device__ __align__(16) float g_ssrc  [N_NODES * HEADS];
__device__ __align__(16) float g_sdst  [N_NODES * HEADS];
__device__ float g_rlog  [NUM_REL * HEADS];
__device__ int   g_cnt   [N_NODES];
__device__ int   g_rowptr[N_NODES];
__device__ int   g_cursor[N_NODES];
__device__ int   g_csre  [E_EDGES];
__device__ unsigned char g_need_out[N_NODES];   // monotone marks
__device__ unsigned char g_need_h  [N_NODES];
__device__ int   g_hidx  [N_NODES];
__device__ int   g_hlist [N_NODES];
__device__ int   g_ulist [N_NODES];
__device__ int   g_olist [MAX_OUT];
__device__ int   g_hcount;
__device__ int   g_ucount;
__device__ int   g_ocount;
__device__ int   g_ebase;
__device__ int   g_is64;

// ---------------- helpers ----------------
__device__ __forceinline__ int load_idx(const void* p, int i) {
    if (g_is64) return (int)((const long long*)p)[i];
    return ((const int*)p)[i];
}
__device__ __forceinline__ float warp_reduce(float v) {
    #pragma unroll
    for (int o = 16; o > 0; o >>= 1) v += __shfl_down_sync(0xffffffffu, v, o);
    return v;
}
__device__ __forceinline__ uint32_t smem_u32(const void* p) {
    uint32_t a;
    asm("{ .reg .u64 t; cvta.to.shared.u64 t, %1; cvt.u32.u64 %0, t; }" : "=r"(a) : "l"(p));
    return a;
}
__device__ __forceinline__ void cp_async16(uint32_t s, const void* g) {
    asm volatile("cp.async.cg.shared.global [%0], [%1], 16;" :: "r"(s), "l"(g));
}
__device__ __forceinline__ void cp_commit() {
    asm volatile("cp.async.commit_group;" ::: "memory");
}
template<int NN> __device__ __forceinline__ void cp_wait() {
    asm volatile("cp.async.wait_group %0;" :: "n"(NN) : "memory");
}
__device__ __forceinline__ void ldm_x4(uint32_t* r, uint32_t addr) {
    asm volatile("ldmatrix.sync.aligned.m8n8.x4.shared.b16 {%0,%1,%2,%3}, [%4];"
                 : "=r"(r[0]), "=r"(r[1]), "=r"(r[2]), "=r"(r[3]) : "r"(addr));
}
__device__ __forceinline__ void mma16816(float* d, const uint32_t* a, const uint32_t* b) {
    asm volatile(
        "mma.sync.aligned.m16n8k16.row.col.f32.f16.f16.f32 "
        "{%0,%1,%2,%3}, {%4,%5,%6,%7}, {%8,%9}, {%0,%1,%2,%3};"
        : "+f"(d[0]), "+f"(d[1]), "+f"(d[2]), "+f"(d[3])
        : "r"(a[0]), "r"(a[1]), "r"(a[2]), "r"(a[3]), "r"(b[0]), "r"(b[1]));
}

// ---------------- 1) init + dtype detect + mark distmult endpoints ----------------
__global__ void init_mark_kernel(const void* __restrict__ si, const void* __restrict__ di) {
    __shared__ int s_is64;
    const int t = threadIdx.x;
    const int tid = blockIdx.x * blockDim.x + t;
    if (t == 0) {
        const long long* p = (const long long*)si;
        int ok = 1;
        for (int i = 0; i < 64; i++) {
            long long v = p[i];
            if (v < 0 || v >= N_NODES) { ok = 0; break; }
        }
        s_is64 = ok;
        if (blockIdx.x == 0) g_is64 = ok;
    }
    if (tid < N_NODES * HEADS) { g_ssrc[tid] = 0.0f; g_sdst[tid] = 0.0f; }
    if (tid < N_NODES) g_cnt[tid] = 0;
    if (tid == 0) { g_hcount = 0; g_ucount = 0; g_ocount = 0; g_ebase = 0; }
    __syncthreads();
    const int is64 = s_is64;
    if (tid < BATCH) {
        int n = is64 ? (int)((const long long*)si)[tid] : ((const int*)si)[tid];
        g_need_out[n] = 1;
    } else if (tid < 2 * BATCH) {
        int i = tid - BATCH;
        int n = is64 ? (int)((const long long*)di)[i] : ((const int*)di)[i];
        g_need_out[n] = 1;
    }
}

// ---------------- 2) mark needed h rows + count gated in-edges ----------------
__global__ void mark_src_kernel(const void* __restrict__ ei) {
    int e = blockIdx.x * blockDim.x + threadIdx.x;
    if (e >= E_EDGES) return;
    int d = load_idx(ei, E_EDGES + e);
    if (g_need_out[d]) {
        int s = load_idx(ei, e);
        g_need_h[s] = 1;
        atomicAdd(&g_cnt[d], 1);
    }
}

// ---------------- 3) compact lists + allocate CSR segments (no scan needed) -------
__global__ void compact_kernel() {
    int n = blockIdx.x * blockDim.x + threadIdx.x;
    if (n >= N_NODES) return;
    unsigned char nh = g_need_h[n];
    unsigned char no = g_need_out[n];
    if (nh) {
        int p = atomicAdd(&g_hcount, 1);
        g_hlist[p] = n;
        g_hidx[n] = p;
    }
    if (nh || no) {
        int p = atomicAdd(&g_ucount, 1);
        g_ulist[p] = n;
    }
    if (no) {
        int p = atomicAdd(&g_ocount, 1);
        g_olist[p] = n;
        int base = atomicAdd(&g_ebase, g_cnt[n]);   // segment allocation
        g_rowptr[n] = base;
        g_cursor[n] = base;
    }
}

// ---------------- 4) c vectors + rel logits (merged) ----------------
__global__ void cvec_rel_kernel(const float* __restrict__ Wm,
                                const float* __restrict__ a_src,
                                const float* __restrict__ a_dst,
                                const float* __restrict__ rel_feat,
                                const float* __restrict__ a_rel) {
    int gwid = (blockIdx.x * blockDim.x + threadIdx.x) >> 5;
    int lane = threadIdx.x & 31;
    if (gwid < IN_DIM * HEADS) {
        int k = gwid >> 2, h = gwid & 3;
        const float* wrow = Wm + (size_t)k * HID + h * OUT_DIM;
        const float* as = a_src + h * OUT_DIM;
        const float* ad = a_dst + h * OUT_DIM;
        float cs = 0.f, cd = 0.f;
        for (int d = lane; d < OUT_DIM; d += 32) {
            float w = wrow[d];
            cs = fmaf(w, as[d], cs);
            cd = fmaf(w, ad[d], cd);
        }
        cs = warp_reduce(cs);
        cd = warp_reduce(cd);
        if (lane == 0) { g_csrc[k * 4 + h] = cs; g_cdst[k * 4 + h] = cd; }
    } else if (gwid < IN_DIM * HEADS + NUM_REL * HEADS) {
        int w2 = gwid - IN_DIM * HEADS;
        int r = w2 >> 2, h = w2 & 3;
        const float* rp = rel_feat + (size_t)r * HID + h * OUT_DIM;
        const float* ar = a_rel + h * OUT_DIM;
        float s = 0.f;
        for (int d = lane; d < OUT_DIM; d += 32) s = fmaf(rp[d], ar[d], s);
        s = warp_reduce(s);
        if (lane == 0) g_rlog[w2] = s;
    }
}

// ---------------- 5) s-pass over union (butterfly + atomics) + W^T ----------------
__global__ void __launch_bounds__(256) split_fused_kernel(const float* __restrict__ A,
                                                          const float* __restrict__ Wm) {
    const int bid = blockIdx.x;
    if (bid < SPLITA_BLOCKS) {
        const int t = threadIdx.x;
        const int lane = t & 31;
        const int ulen = g_ucount;
        float4 cs[4], cd[4];
        #pragma unroll
        for (int q = 0; q < 4; q++) {
            cs[q] = ((const float4*)g_csrc)[t * 4 + q];
            cd[q] = ((const float4*)g_cdst)[t * 4 + q];
        }
        for (int li = bid; li < ulen; li += SPLITA_BLOCKS) {
            const int n = g_ulist[li];
            float4 a = ((const float4*)(A + (size_t)n * IN_DIM))[t];
            float av[4] = {a.x, a.y, a.z, a.w};
            float ss0 = 0.f, ss1 = 0.f, ss2 = 0.f, ss3 = 0.f;
            float sd0 = 0.f, sd1 = 0.f, sd2 = 0.f, sd3 = 0.f;
            #pragma unroll
            for (int q = 0; q < 4; q++) {
                ss0 = fmaf(av[q], cs[q].x, ss0); ss1 = fmaf(av[q], cs[q].y, ss1);
                ss2 = fmaf(av[q], cs[q].z, ss2); ss3 = fmaf(av[q], cs[q].w, ss3);
                sd0 = fmaf(av[q], cd[q].x, sd0); sd1 = fmaf(av[q], cd[q].y, sd1);
                sd2 = fmaf(av[q], cd[q].z, sd2); sd3 = fmaf(av[q], cd[q].w, sd3);
            }
            if (g_need_h[n]) {
                __half2* ph = (__half2*)(g_Ah + (size_t)n * IN_DIM) + t * 2;
                ph[0] = __halves2half2(__float2half(a.x), __float2half(a.y));
                ph[1] = __halves2half2(__float2half(a.z), __float2half(a.w));
            }
            #pragma unroll
            for (int o = 16; o > 0; o >>= 1) {
                ss0 += __shfl_xor_sync(0xffffffffu, ss0, o);
                ss1 += __shfl_xor_sync(0xffffffffu, ss1, o);
                ss2 += __shfl_xor_sync(0xffffffffu, ss2, o);
                ss3 += __shfl_xor_sync(0xffffffffu, ss3, o);
                sd0 += __shfl_xor_sync(0xffffffffu, sd0, o);
                sd1 += __shfl_xor_sync(0xffffffffu, sd1, o);
                sd2 += __shfl_xor_sync(0xffffffffu, sd2, o);
                sd3 += __shfl_xor_sync(0xffffffffu, sd3, o);
            }
            if (lane == 0) {
                atomicAdd(&g_ssrc[n * 4 + 0], ss0);
                atomicAdd(&g_ssrc[n * 4 + 1], ss1);
                atomicAdd(&g_ssrc[n * 4 + 2], ss2);
                atomicAdd(&g_ssrc[n * 4 + 3], ss3);
                atomicAdd(&g_sdst[n * 4 + 0], sd0);
                atomicAdd(&g_sdst[n * 4 + 1], sd1);
                atomicAdd(&g_sdst[n * 4 + 2], sd2);
                atomicAdd(&g_sdst[n * 4 + 3], sd3);
            }
        }
    } else {
        __shared__ float tile[32][33];
        const int b = bid - SPLITA_BLOCKS;
        const int tx = threadIdx.x & 31;
        const int ty = threadIdx.x >> 5;
        const int k0 = (b % (IN_DIM / 32)) * 32;
        const int n0 = (b / (IN_DIM / 32)) * 32;
        #pragma unroll
        for (int j = 0; j < 4; j++) {
            int k = k0 + ty + j * 8;
            int n = n0 + tx;
            tile[ty + j * 8][tx] = (n < HID) ? Wm[(size_t)k * HID + n] : 0.0f;
        }
        __syncthreads();
        #pragma unroll
        for (int j = 0; j < 4; j++) {
            int n = n0 + ty + j * 8;
            int k = k0 + tx;
            g_Bh[(size_t)n * IN_DIM + k] = __float2half(tile[tx][ty + j * 8]);
        }
    }
}

// ---------------- 6) HMMA GEMM: BM=128, BN=128, fp16 output ----------------
__global__ void __launch_bounds__(256) gemm_mma_kernel() {
    __shared__ int rowlist[BM];
    const int len = g_hcount;
    const int mt0 = blockIdx.y * BM;
    if (mt0 >= len) return;

    extern __shared__ char smem[];
    const uint32_t sbase = smem_u32(smem);
    const int t = threadIdx.x;
    const int lane = t & 31;
    const int warp = t >> 5;
    const int wm = warp >> 1;
    const int wn = warp & 1;
    const int n0 = blockIdx.x * BN;

    if (t < BM) {
        int rr = mt0 + t;
        rowlist[t] = g_hlist[rr < len ? rr : len - 1];
    }
    __syncthreads();

    float acc[2][8][4];
    #pragma unroll
    for (int mi = 0; mi < 2; mi++)
        #pragma unroll
        for (int nj = 0; nj < 8; nj++)
            #pragma unroll
            for (int q = 0; q < 4; q++) acc[mi][nj][q] = 0.0f;

    auto load_chunk = [&](int c, int buf) {
        #pragma unroll
        for (int i = 0; i < 2; i++) {
            int lin = i * 256 + t;
            int r = lin >> 2, seg = lin & 3;
            int node = rowlist[r];
            size_t go = (size_t)node * IN_DIM + c * BK + seg * 8;
            uint32_t so = (uint32_t)(r * A_STRIDE + seg * 16);
            cp_async16(sbase + SA_OFF(buf) + so, g_Ah + go);
        }
        #pragma unroll
        for (int i = 0; i < 2; i++) {
            int lin = i * 256 + t;
            int r = lin >> 2, seg = lin & 3;
            size_t go = (size_t)(n0 + r) * IN_DIM + c * BK + seg * 8;
            uint32_t so = (uint32_t)(r * A_STRIDE + seg * 16);
            cp_async16(sbase + SB_OFF(buf) + so, g_Bh + go);
        }
        cp_commit();
    };

    load_chunk(0, 0);
    load_chunk(1, 1);

    for (int c = 0; c < NCHUNK; c++) {
        if (c == NCHUNK - 1) cp_wait<0>(); else cp_wait<1>();
        __syncthreads();
        const int buf = c & 1;

        #pragma unroll
        for (int k16 = 0; k16 < BK; k16 += 16) {
            uint32_t af[2][4];
            #pragma unroll
            for (int mi = 0; mi < 2; mi++) {
                int r = wm * 32 + mi * 16 + (lane & 7) + ((lane >> 3) & 1) * 8;
                int colB = (k16 + (lane >> 4) * 8) * 2;
                ldm_x4(af[mi], sbase + SA_OFF(buf) + r * A_STRIDE + colB);
            }
            uint32_t bf[8][2];
            #pragma unroll
            for (int pr = 0; pr < 4; pr++) {
                uint32_t r4[4];
                int n = wn * 64 + pr * 16 + ((lane >> 4) & 1) * 8 + (lane & 7);
                int colB = (k16 + ((lane >> 3) & 1) * 8) * 2;
                ldm_x4(r4, sbase + SB_OFF(buf) + n * A_STRIDE + colB);
                bf[pr * 2 + 0][0] = r4[0]; bf[pr * 2 + 0][1] = r4[1];
                bf[pr * 2 + 1][0] = r4[2]; bf[pr * 2 + 1][1] = r4[3];
            }
            #pragma unroll
            for (int mi = 0; mi < 2; mi++)
                #pragma unroll
                for (int nj = 0; nj < 8; nj++)
                    mma16816(acc[mi][nj], af[mi], bf[nj]);
        }
        __syncthreads();
        if (c + 2 < NCHUNK) load_chunk(c + 2, buf);
    }

    // epilogue: fp16 stores
    #pragma unroll
    for (int mi = 0; mi < 2; mi++)
        #pragma unroll
        for (int nj = 0; nj < 8; nj++) {
            int tileN = n0 + wn * 64 + nj * 8;
            if (tileN >= HID) continue;
            int col = tileN + 2 * (lane & 3);
            int lr0 = wm * 32 + mi * 16 + (lane >> 2);
            if (mt0 + lr0 < len)
                *(__half2*)(g_h + (size_t)(mt0 + lr0) * HID + col) =
                    __floats2half2_rn(acc[mi][nj][0], acc[mi][nj][1]);
            if (mt0 + lr0 + 8 < len)
                *(__half2*)(g_h + (size_t)(mt0 + lr0 + 8) * HID + col) =
                    __floats2half2_rn(acc[mi][nj][2], acc[mi][nj][3]);
        }
}

// ---------------- 7) CSR fill (gated) ----------------
__global__ void fill_kernel(const void* __restrict__ ei) {
    int e = blockIdx.x * blockDim.x + threadIdx.x;
    if (e >= E_EDGES) return;
    int d = load_idx(ei, E_EDGES + e);
    if (!g_need_out[d]) return;
    int pos = atomicAdd(&g_cursor[d], 1);
    g_csre[pos] = e;
}

// ---------------- 8) fused softmax + aggregate (single edge pass, fp16 h) ----------
__global__ void __launch_bounds__(256) agg_kernel(const void* __restrict__ ei,
                                                  const void* __restrict__ et) {
    int o    = (blockIdx.x * blockDim.x + threadIdx.x) >> 5;
    int lane = threadIdx.x & 31;
    if (o >= g_ocount) return;
    int n = g_olist[o];
    int rp0 = g_rowptr[n];
    int rp1 = rp0 + g_cnt[n];

    // h row = 800 fp16 = 100 uint4 (8 halves each); lane covers c = lane + it*32, it<4
    float acc[4][8];
    #pragma unroll
    for (int it = 0; it < 4; it++)
        #pragma unroll
        for (int q = 0; q < 8; q++) acc[it][q] = 0.0f;
    float dn0 = 0.f, dn1 = 0.f, dn2 = 0.f, dn3 = 0.f;

    for (int j = rp0; j < rp1; j++) {
        int e = g_csre[j];
        int s = load_idx(ei, e);
        float ev_l = 0.f;
        if (lane < 4) {
            int r = load_idx(et, e);
            float x = g_ssrc[s * 4 + lane] + g_sdst[n * 4 + lane] + g_rlog[r * 4 + lane];
            x = (x >= 0.f) ? x : NEG_SLOPE * x;
            ev_l = expf(x);
        }
        float e0 = __shfl_sync(0xffffffffu, ev_l, 0);
        float e1 = __shfl_sync(0xffffffffu, ev_l, 1);
        float e2 = __shfl_sync(0xffffffffu, ev_l, 2);
        float e3 = __shfl_sync(0xffffffffu, ev_l, 3);
        dn0 += e0; dn1 += e1; dn2 += e2; dn3 += e3;
        int hrow = g_hidx[s];
        const uint4* hp = (const uint4*)(g_h + (size_t)hrow * HID);
        #pragma unroll
        for (int it = 0; it < 4; it++) {
            int c = lane + it * 32;
            if (c < 100) {                  // 100 uint4 per row; 25 per head
                float a = (c < 25) ? e0 : (c < 50) ? e1 : (c < 75) ? e2 : e3;
                uint4 v = hp[c];
                float2 f0 = __half22float2(*(const __half2*)&v.x);
                float2 f1 = __half22float2(*(const __half2*)&v.y);
                float2 f2 = __half22float2(*(const __half2*)&v.z);
                float2 f3 = __half22float2(*(const __half2*)&v.w);
                acc[it][0] = fmaf(a, f0.x, acc[it][0]);
                acc[it][1] = fmaf(a, f0.y, acc[it][1]);
                acc[it][2] = fmaf(a, f1.x, acc[it][2]);
                acc[it][3] = fmaf(a, f1.y, acc[it][3]);
                acc[it][4] = fmaf(a, f2.x, acc[it][4]);
                acc[it][5] = fmaf(a, f2.y, acc[it][5]);
                acc[it][6] = fmaf(a, f3.x, acc[it][6]);
                acc[it][7] = fmaf(a, f3.y, acc[it][7]);
            }
        }
    }
    float r0 = (dn0 > 0.f) ? 1.0f / dn0 : 0.0f;
    float r1 = (dn1 > 0.f) ? 1.0f / dn1 : 0.0f;
    float r2 = (dn2 > 0.f) ? 1.0f / dn2 : 0.0f;
    float r3 = (dn3 > 0.f) ? 1.0f / dn3 : 0.0f;
    float4* op = (float4*)(g_out + (size_t)n * HID);
    #pragma unroll
    for (int it = 0; it < 4; it++) {
        int c = lane + it * 32;
        if (c < 100) {
            float r = (c < 25) ? r0 : (c < 50) ? r1 : (c < 75) ? r2 : r3;
            op[c * 2]     = make_float4(acc[it][0] * r, acc[it][1] * r,
                                        acc[it][2] * r, acc[it][3] * r);
            op[c * 2 + 1] = make_float4(acc[it][4] * r, acc[it][5] * r,
                                        acc[it][6] * r, acc[it][7] * r);
        }
    }
}

// ---------------- 9) DistMult ----------------
__global__ void distmult_kernel(const float* __restrict__ bias,
                                const float* __restrict__ rel_emb,
                                const void* __restrict__ si,
                                const void* __restrict__ ri,
                                const void* __restrict__ di,
                                float* __restrict__ out) {
    int wid  = (blockIdx.x * blockDim.x + threadIdx.x) >> 5;
    int lane = threadIdx.x & 31;
    if (wid >= BATCH) return;
    int s = load_idx(si, wid);
    int r = load_idx(ri, wid);
    int d = load_idx(di, wid);
    const float* ps = g_out + (size_t)s * HID;
    const float* pd = g_out + (size_t)d * HID;
    const float* pr = rel_emb + (size_t)r * HID;
    float acc = 0.f;
    for (int k = lane; k < HID; k += 32) {
        float b = bias[k];
        acc = fmaf((ps[k] + b) * pr[k], (pd[k] + b), acc);
    }
    acc = warp_reduce(acc);
    if (lane == 0) out[wid] = acc;
}

// ---------------- launch ----------------
extern "C" void kernel_launch(void* const* d_in, const int* in_sizes, int n_in,
                              void* d_out, int out_size) {
    const float* node_emb   = (const float*)d_in[0];
    const float* Wm         = (const float*)d_in[1];
    const float* bias       = (const float*)d_in[2];
    const float* a_src      = (const float*)d_in[3];
    const float* a_dst      = (const float*)d_in[4];
    const float* a_rel      = (const float*)d_in[5];
    const float* rel_feat   = (const float*)d_in[6];
    const float* rel_emb    = (const float*)d_in[7];
    const void*  edge_index = d_in[8];
    const void*  edge_type  = d_in[9];
    const void*  src_ids    = d_in[10];
    const void*  rel_ids    = d_in[11];
    const void*  dst_ids    = d_in[12];
    float* out = (float*)d_out;

    cudaFuncSetAttribute(gemm_mma_kernel,
                         cudaFuncAttributeMaxDynamicSharedMemorySize, SM_TOT);

    init_mark_kernel<<<(N_NODES * HEADS + 255) / 256, 256>>>(src_ids, dst_ids);
    mark_src_kernel<<<(E_EDGES + 255) / 256, 256>>>(edge_index);
    compact_kernel<<<(N_NODES + 255) / 256, 256>>>();
    cvec_rel_kernel<<<((IN_DIM * HEADS + NUM_REL * HEADS) * 32 + 255) / 256, 256>>>(
        Wm, a_src, a_dst, rel_feat, a_rel);
    split_fused_kernel<<<SPLITA_BLOCKS + SPLITB_BLOCKS, 256>>>(node_emb, Wm);

    dim3 ggrid(NT_N, NT_M);
    gemm_mma_kernel<<<ggrid, 256, SM_TOT>>>();

    fill_kernel<<<(E_EDGES + 255) / 256, 256>>>(edge_index);
    agg_kernel<<<(MAX_OUT * 32 + 255) / 256, 256>>>(edge_index, edge_type);
    distmult_kernel<<<(BATCH * 32 + 255) / 256, 256>>>(bias, rel_emb,
                                                       src_ids, rel_ids, dst_ids, out);
}

// round 15
// speedup vs baseline: 1.2311x; 1.0090x over previous
#include <cuda_runtime.h>
#include <cuda_fp16.h>
#include <cfloat>
#include <cstdint>

#define N_NODES 50000
#define IN_DIM  1024
#define E_EDGES 100000
#define NUM_REL 40
#define HEADS   4
#define OUT_DIM 200
#define HID     800
#define BATCH   8192
#define NEG_SLOPE 0.2f

#define BM 128
#define BN 128
#define BK 32
#define NCHUNK (IN_DIM / BK)            // 32
#define NT_M ((N_NODES + BM - 1) / BM)
#define NT_N 7
#define PAD_N (NT_N * BN)               // 896

#define A_STRIDE 80
#define A_VER_SZ (128 * A_STRIDE)       // 10240
#define B_VER_SZ (128 * A_STRIDE)       // 10240
#define SA_OFF(buf) ((buf) * A_VER_SZ)
#define SB_OFF(buf) (3 * A_VER_SZ + (buf) * B_VER_SZ)
#define SM_TOT (3 * A_VER_SZ + 3 * B_VER_SZ)   // 61440

#define SPLITA_BLOCKS 592
#define SPLITB_BLOCKS ((IN_DIM / 32) * (PAD_N / 32))   // 896
#define FILL_BLOCKS  ((E_EDGES + 255) / 256)           // 391
#define INIT_BLOCKS  ((N_NODES * HEADS + 255) / 256)   // 782
#define CVEC_BLOCKS  (((IN_DIM + NUM_REL) * HEADS + 7) / 8)  // 532
#define MAX_OUT (2 * BATCH)

// ---------------- scratch (device globals) ----------------
__device__ __align__(16) __half g_h  [(size_t)N_NODES * HID];  // compacted h rows (fp16)
__device__ __align__(16) float g_out[(size_t)N_NODES * HID];   // node-indexed
__device__ __align__(16) __half g_Ah[(size_t)N_NODES * IN_DIM];
__device__ __align__(16) __half g_Bh[(size_t)PAD_N * IN_DIM];
__device__ __align__(16) float g_csrc[IN_DIM * HEADS];
__device__ __align__(16) float g_cdst[IN_DIM * HEADS];
__device__ __align__(16) float g_ssrc  [N_NODES * HEADS];
__device__ __align__(16) float g_sdst  [N_NODES * HEADS];
__device__ float g_rlog  [NUM_REL * HEADS];
__device__ int   g_cnt   [N_NODES];
__device__ int   g_rowptr[N_NODES];
__device__ int   g_cursor[N_NODES];
__device__ int   g_csre  [E_EDGES];
__device__ unsigned char g_need_out[N_NODES];   // monotone marks
__device__ unsigned char g_need_h  [N_NODES];
__device__ int   g_hidx  [N_NODES];
__device__ int   g_hlist [N_NODES];
__device__ int   g_ulist [N_NODES];
__device__ int   g_olist [MAX_OUT];
__device__ int   g_hcount;
__device__ int   g_ucount;
__device__ int   g_ocount;
__device__ int   g_ebase;
__device__ int   g_is64;

// ---------------- helpers ----------------
__device__ __forceinline__ int load_idx(const void* p, int i) {
    if (g_is64) return (int)((const long long*)p)[i];
    return ((const int*)p)[i];
}
__device__ __forceinline__ float warp_reduce(float v) {
    #pragma unroll
    for (int o = 16; o > 0; o >>= 1) v += __shfl_down_sync(0xffffffffu, v, o);
    return v;
}
__device__ __forceinline__ uint32_t smem_u32(const void* p) {
    uint32_t a;
    asm("{ .reg .u64 t; cvta.to.shared.u64 t, %1; cvt.u32.u64 %0, t; }" : "=r"(a) : "l"(p));
    return a;
}
__device__ __forceinline__ void cp_async16(uint32_t s, const void* g) {
    asm volatile("cp.async.cg.shared.global [%0], [%1], 16;" :: "r"(s), "l"(g));
}
__device__ __forceinline__ void cp_commit() {
    asm volatile("cp.async.commit_group;" ::: "memory");
}
template<int NN> __device__ __forceinline__ void cp_wait() {
    asm volatile("cp.async.wait_group %0;" :: "n"(NN) : "memory");
}
__device__ __forceinline__ void ldm_x4(uint32_t* r, uint32_t addr) {
    asm volatile("ldmatrix.sync.aligned.m8n8.x4.shared.b16 {%0,%1,%2,%3}, [%4];"
                 : "=r"(r[0]), "=r"(r[1]), "=r"(r[2]), "=r"(r[3]) : "r"(addr));
}
__device__ __forceinline__ void mma16816(float* d, const uint32_t* a, const uint32_t* b) {
    asm volatile(
        "mma.sync.aligned.m16n8k16.row.col.f32.f16.f16.f32 "
        "{%0,%1,%2,%3}, {%4,%5,%6,%7}, {%8,%9}, {%0,%1,%2,%3};"
        : "+f"(d[0]), "+f"(d[1]), "+f"(d[2]), "+f"(d[3])
        : "r"(a[0]), "r"(a[1]), "r"(a[2]), "r"(a[3]), "r"(b[0]), "r"(b[1]));
}

// ---------------- 1) init + dtype + mark endpoints + cvec/rel (merged) -------------
__global__ void init_mark_cvec_kernel(const void* __restrict__ si, const void* __restrict__ di,
                                      const float* __restrict__ Wm,
                                      const float* __restrict__ a_src,
                                      const float* __restrict__ a_dst,
                                      const float* __restrict__ rel_feat,
                                      const float* __restrict__ a_rel) {
    const int bid = blockIdx.x;
    const int t = threadIdx.x;
    if (bid < INIT_BLOCKS) {
        __shared__ int s_is64;
        const int tid = bid * 256 + t;
        if (t == 0) {
            const long long* p = (const long long*)si;
            int ok = 1;
            for (int i = 0; i < 64; i++) {
                long long v = p[i];
                if (v < 0 || v >= N_NODES) { ok = 0; break; }
            }
            s_is64 = ok;
            if (bid == 0) g_is64 = ok;
        }
        if (tid < N_NODES * HEADS) { g_ssrc[tid] = 0.0f; g_sdst[tid] = 0.0f; }
        if (tid < N_NODES) g_cnt[tid] = 0;
        if (tid == 0) { g_hcount = 0; g_ucount = 0; g_ocount = 0; g_ebase = 0; }
        __syncthreads();
        const int is64 = s_is64;
        if (tid < BATCH) {
            int n = is64 ? (int)((const long long*)si)[tid] : ((const int*)si)[tid];
            g_need_out[n] = 1;
        } else if (tid < 2 * BATCH) {
            int i = tid - BATCH;
            int n = is64 ? (int)((const long long*)di)[i] : ((const int*)di)[i];
            g_need_out[n] = 1;
        }
    } else {
        int gwid = (bid - INIT_BLOCKS) * 8 + (t >> 5);
        int lane = t & 31;
        if (gwid < IN_DIM * HEADS) {
            int k = gwid >> 2, h = gwid & 3;
            const float* wrow = Wm + (size_t)k * HID + h * OUT_DIM;
            const float* as = a_src + h * OUT_DIM;
            const float* ad = a_dst + h * OUT_DIM;
            float cs = 0.f, cd = 0.f;
            for (int d = lane; d < OUT_DIM; d += 32) {
                float w = wrow[d];
                cs = fmaf(w, as[d], cs);
                cd = fmaf(w, ad[d], cd);
            }
            cs = warp_reduce(cs);
            cd = warp_reduce(cd);
            if (lane == 0) { g_csrc[k * 4 + h] = cs; g_cdst[k * 4 + h] = cd; }
        } else if (gwid < (IN_DIM + NUM_REL) * HEADS) {
            int w2 = gwid - IN_DIM * HEADS;
            int r = w2 >> 2, h = w2 & 3;
            const float* rp = rel_feat + (size_t)r * HID + h * OUT_DIM;
            const float* ar = a_rel + h * OUT_DIM;
            float s = 0.f;
            for (int d = lane; d < OUT_DIM; d += 32) s = fmaf(rp[d], ar[d], s);
            s = warp_reduce(s);
            if (lane == 0) g_rlog[w2] = s;
        }
    }
}

// ---------------- 2) mark needed h rows + count gated in-edges ----------------
__global__ void mark_src_kernel(const void* __restrict__ ei) {
    int e = blockIdx.x * blockDim.x + threadIdx.x;
    if (e >= E_EDGES) return;
    int d = load_idx(ei, E_EDGES + e);
    if (g_need_out[d]) {
        int s = load_idx(ei, e);
        g_need_h[s] = 1;
        atomicAdd(&g_cnt[d], 1);
    }
}

// ---------------- 3) compact lists + allocate CSR segments ----------------
__global__ void compact_kernel() {
    int n = blockIdx.x * blockDim.x + threadIdx.x;
    if (n >= N_NODES) return;
    unsigned char nh = g_need_h[n];
    unsigned char no = g_need_out[n];
    if (nh) {
        int p = atomicAdd(&g_hcount, 1);
        g_hlist[p] = n;
        g_hidx[n] = p;
    }
    if (nh || no) {
        int p = atomicAdd(&g_ucount, 1);
        g_ulist[p] = n;
    }
    if (no) {
        int p = atomicAdd(&g_ocount, 1);
        g_olist[p] = n;
        int base = atomicAdd(&g_ebase, g_cnt[n]);
        g_rowptr[n] = base;
        g_cursor[n] = base;
    }
}

// ---------------- 4) s-pass + W^T + CSR fill (merged, three block ranges) ---------
__global__ void __launch_bounds__(256) split_fused_kernel(const float* __restrict__ A,
                                                          const float* __restrict__ Wm,
                                                          const void* __restrict__ ei) {
    const int bid = blockIdx.x;
    if (bid < SPLITA_BLOCKS) {
        const int t = threadIdx.x;
        const int lane = t & 31;
        const int ulen = g_ucount;
        float4 cs[4], cd[4];
        #pragma unroll
        for (int q = 0; q < 4; q++) {
            cs[q] = ((const float4*)g_csrc)[t * 4 + q];
            cd[q] = ((const float4*)g_cdst)[t * 4 + q];
        }
        for (int li = bid; li < ulen; li += SPLITA_BLOCKS) {
            const int n = g_ulist[li];
            float4 a = ((const float4*)(A + (size_t)n * IN_DIM))[t];
            float av[4] = {a.x, a.y, a.z, a.w};
            float ss0 = 0.f, ss1 = 0.f, ss2 = 0.f, ss3 = 0.f;
            float sd0 = 0.f, sd1 = 0.f, sd2 = 0.f, sd3 = 0.f;
            #pragma unroll
            for (int q = 0; q < 4; q++) {
                ss0 = fmaf(av[q], cs[q].x, ss0); ss1 = fmaf(av[q], cs[q].y, ss1);
                ss2 = fmaf(av[q], cs[q].z, ss2); ss3 = fmaf(av[q], cs[q].w, ss3);
                sd0 = fmaf(av[q], cd[q].x, sd0); sd1 = fmaf(av[q], cd[q].y, sd1);
                sd2 = fmaf(av[q], cd[q].z, sd2); sd3 = fmaf(av[q], cd[q].w, sd3);
            }
            if (g_need_h[n]) {
                __half2* ph = (__half2*)(g_Ah + (size_t)n * IN_DIM) + t * 2;
                ph[0] = __halves2half2(__float2half(a.x), __float2half(a.y));
                ph[1] = __halves2half2(__float2half(a.z), __float2half(a.w));
            }
            #pragma unroll
            for (int o = 16; o > 0; o >>= 1) {
                ss0 += __shfl_xor_sync(0xffffffffu, ss0, o);
                ss1 += __shfl_xor_sync(0xffffffffu, ss1, o);
                ss2 += __shfl_xor_sync(0xffffffffu, ss2, o);
                ss3 += __shfl_xor_sync(0xffffffffu, ss3, o);
                sd0 += __shfl_xor_sync(0xffffffffu, sd0, o);
                sd1 += __shfl_xor_sync(0xffffffffu, sd1, o);
                sd2 += __shfl_xor_sync(0xffffffffu, sd2, o);
                sd3 += __shfl_xor_sync(0xffffffffu, sd3, o);
            }
            if (lane == 0) {
                atomicAdd(&g_ssrc[n * 4 + 0], ss0);
                atomicAdd(&g_ssrc[n * 4 + 1], ss1);
                atomicAdd(&g_ssrc[n * 4 + 2], ss2);
                atomicAdd(&g_ssrc[n * 4 + 3], ss3);
                atomicAdd(&g_sdst[n * 4 + 0], sd0);
                atomicAdd(&g_sdst[n * 4 + 1], sd1);
                atomicAdd(&g_sdst[n * 4 + 2], sd2);
                atomicAdd(&g_sdst[n * 4 + 3], sd3);
            }
        }
    } else if (bid < SPLITA_BLOCKS + SPLITB_BLOCKS) {
        __shared__ float tile[32][33];
        const int b = bid - SPLITA_BLOCKS;
        const int tx = threadIdx.x & 31;
        const int ty = threadIdx.x >> 5;
        const int k0 = (b % (IN_DIM / 32)) * 32;
        const int n0 = (b / (IN_DIM / 32)) * 32;
        #pragma unroll
        for (int j = 0; j < 4; j++) {
            int k = k0 + ty + j * 8;
            int n = n0 + tx;
            tile[ty + j * 8][tx] = (n < HID) ? Wm[(size_t)k * HID + n] : 0.0f;
        }
        __syncthreads();
        #pragma unroll
        for (int j = 0; j < 4; j++) {
            int n = n0 + ty + j * 8;
            int k = k0 + tx;
            g_Bh[(size_t)n * IN_DIM + k] = __float2half(tile[tx][ty + j * 8]);
        }
    } else {
        // CSR fill
        int e = (bid - SPLITA_BLOCKS - SPLITB_BLOCKS) * 256 + threadIdx.x;
        if (e < E_EDGES) {
            int d = load_idx(ei, E_EDGES + e);
            if (g_need_out[d]) {
                int pos = atomicAdd(&g_cursor[d], 1);
                g_csre[pos] = e;
            }
        }
    }
}

// ---------------- 5) HMMA GEMM: 3-stage pipeline, fp16 output ----------------
__global__ void __launch_bounds__(256) gemm_mma_kernel() {
    __shared__ int rowlist[BM];
    const int len = g_hcount;
    const int mt0 = blockIdx.y * BM;
    if (mt0 >= len) return;

    extern __shared__ char smem[];
    const uint32_t sbase = smem_u32(smem);
    const int t = threadIdx.x;
    const int lane = t & 31;
    const int warp = t >> 5;
    const int wm = warp >> 1;
    const int wn = warp & 1;
    const int n0 = blockIdx.x * BN;

    if (t < BM) {
        int rr = mt0 + t;
        rowlist[t] = g_hlist[rr < len ? rr : len - 1];
    }
    __syncthreads();

    float acc[2][8][4];
    #pragma unroll
    for (int mi = 0; mi < 2; mi++)
        #pragma unroll
        for (int nj = 0; nj < 8; nj++)
            #pragma unroll
            for (int q = 0; q < 4; q++) acc[mi][nj][q] = 0.0f;

    auto load_chunk = [&](int c, int buf) {
        #pragma unroll
        for (int i = 0; i < 2; i++) {
            int lin = i * 256 + t;
            int r = lin >> 2, seg = lin & 3;
            int node = rowlist[r];
            size_t go = (size_t)node * IN_DIM + c * BK + seg * 8;
            uint32_t so = (uint32_t)(r * A_STRIDE + seg * 16);
            cp_async16(sbase + SA_OFF(buf) + so, g_Ah + go);
        }
        #pragma unroll
        for (int i = 0; i < 2; i++) {
            int lin = i * 256 + t;
            int r = lin >> 2, seg = lin & 3;
            size_t go = (size_t)(n0 + r) * IN_DIM + c * BK + seg * 8;
            uint32_t so = (uint32_t)(r * A_STRIDE + seg * 16);
            cp_async16(sbase + SB_OFF(buf) + so, g_Bh + go);
        }
        cp_commit();
    };

    load_chunk(0, 0);
    load_chunk(1, 1);

    for (int c = 0; c < NCHUNK; c++) {
        if (c == NCHUNK - 1) cp_wait<0>(); else cp_wait<1>();
        __syncthreads();
        // issue next loads into the free third buffer (safe: all warps passed the
        // barrier, so compute of chunk c-1 — which used buffer (c+2)%3 — is done)
        if (c + 2 < NCHUNK) load_chunk(c + 2, (c + 2) % 3);
        const int buf = c % 3;

        #pragma unroll
        for (int k16 = 0; k16 < BK; k16 += 16) {
            uint32_t af[2][4];
            #pragma unroll
            for (int mi = 0; mi < 2; mi++) {
                int r = wm * 32 + mi * 16 + (lane & 7) + ((lane >> 3) & 1) * 8;
                int colB = (k16 + (lane >> 4) * 8) * 2;
                ldm_x4(af[mi], sbase + SA_OFF(buf) + r * A_STRIDE + colB);
            }
            uint32_t bf[8][2];
            #pragma unroll
            for (int pr = 0; pr < 4; pr++) {
                uint32_t r4[4];
                int n = wn * 64 + pr * 16 + ((lane >> 4) & 1) * 8 + (lane & 7);
                int colB = (k16 + ((lane >> 3) & 1) * 8) * 2;
                ldm_x4(r4, sbase + SB_OFF(buf) + n * A_STRIDE + colB);
                bf[pr * 2 + 0][0] = r4[0]; bf[pr * 2 + 0][1] = r4[1];
                bf[pr * 2 + 1][0] = r4[2]; bf[pr * 2 + 1][1] = r4[3];
            }
            #pragma unroll
            for (int mi = 0; mi < 2; mi++)
                #pragma unroll
                for (int nj = 0; nj < 8; nj++)
                    mma16816(acc[mi][nj], af[mi], bf[nj]);
        }
        // no trailing barrier: 3-stage buffering makes the next iteration's
        // leading barrier sufficient
    }

    #pragma unroll
    for (int mi = 0; mi < 2; mi++)
        #pragma unroll
        for (int nj = 0; nj < 8; nj++) {
            int tileN = n0 + wn * 64 + nj * 8;
            if (tileN >= HID) continue;
            int col = tileN + 2 * (lane & 3);
            int lr0 = wm * 32 + mi * 16 + (lane >> 2);
            if (mt0 + lr0 < len)
                *(__half2*)(g_h + (size_t)(mt0 + lr0) * HID + col) =
                    __floats2half2_rn(acc[mi][nj][0], acc[mi][nj][1]);
            if (mt0 + lr0 + 8 < len)
                *(__half2*)(g_h + (size_t)(mt0 + lr0 + 8) * HID + col) =
                    __floats2half2_rn(acc[mi][nj][2], acc[mi][nj][3]);
        }
}

// ---------------- 6) fused softmax + aggregate (single edge pass, fp16 h) ----------
__global__ void __launch_bounds__(256) agg_kernel(const void* __restrict__ ei,
                                                  const void* __restrict__ et) {
    int o    = (blockIdx.x * blockDim.x + threadIdx.x) >> 5;
    int lane = threadIdx.x & 31;
    if (o >= g_ocount) return;
    int n = g_olist[o];
    int rp0 = g_rowptr[n];
    int rp1 = rp0 + g_cnt[n];

    float acc[4][8];
    #pragma unroll
    for (int it = 0; it < 4; it++)
        #pragma unroll
        for (int q = 0; q < 8; q++) acc[it][q] = 0.0f;
    float dn0 = 0.f, dn1 = 0.f, dn2 = 0.f, dn3 = 0.f;

    for (int j = rp0; j < rp1; j++) {
        int e = g_csre[j];
        int s = load_idx(ei, e);
        float ev_l = 0.f;
        if (lane < 4) {
            int r = load_idx(et, e);
            float x = g_ssrc[s * 4 + lane] + g_sdst[n * 4 + lane] + g_rlog[r * 4 + lane];
            x = (x >= 0.f) ? x : NEG_SLOPE * x;
            ev_l = expf(x);
        }
        float e0 = __shfl_sync(0xffffffffu, ev_l, 0);
        float e1 = __shfl_sync(0xffffffffu, ev_l, 1);
        float e2 = __shfl_sync(0xffffffffu, ev_l, 2);
        float e3 = __shfl_sync(0xffffffffu, ev_l, 3);
        dn0 += e0; dn1 += e1; dn2 += e2; dn3 += e3;
        int hrow = g_hidx[s];
        const uint4* hp = (const uint4*)(g_h + (size_t)hrow * HID);
        #pragma unroll
        for (int it = 0; it < 4; it++) {
            int c = lane + it * 32;
            if (c < 100) {
                float a = (c < 25) ? e0 : (c < 50) ? e1 : (c < 75) ? e2 : e3;
                uint4 v = hp[c];
                float2 f0 = __half22float2(*(const __half2*)&v.x);
                float2 f1 = __half22float2(*(const __half2*)&v.y);
                float2 f2 = __half22float2(*(const __half2*)&v.z);
                float2 f3 = __half22float2(*(const __half2*)&v.w);
                acc[it][0] = fmaf(a, f0.x, acc[it][0]);
                acc[it][1] = fmaf(a, f0.y, acc[it][1]);
                acc[it][2] = fmaf(a, f1.x, acc[it][2]);
                acc[it][3] = fmaf(a, f1.y, acc[it][3]);
                acc[it][4] = fmaf(a, f2.x, acc[it][4]);
                acc[it][5] = fmaf(a, f2.y, acc[it][5]);
                acc[it][6] = fmaf(a, f3.x, acc[it][6]);
                acc[it][7] = fmaf(a, f3.y, acc[it][7]);
            }
        }
    }
    float r0 = (dn0 > 0.f) ? 1.0f / dn0 : 0.0f;
    float r1 = (dn1 > 0.f) ? 1.0f / dn1 : 0.0f;
    float r2 = (dn2 > 0.f) ? 1.0f / dn2 : 0.0f;
    float r3 = (dn3 > 0.f) ? 1.0f / dn3 : 0.0f;
    float4* op = (float4*)(g_out + (size_t)n * HID);
    #pragma unroll
    for (int it = 0; it < 4; it++) {
        int c = lane + it * 32;
        if (c < 100) {
            float r = (c < 25) ? r0 : (c < 50) ? r1 : (c < 75) ? r2 : r3;
            op[c * 2]     = make_float4(acc[it][0] * r, acc[it][1] * r,
                                        acc[it][2] * r, acc[it][3] * r);
            op[c * 2 + 1] = make_float4(acc[it][4] * r, acc[it][5] * r,
                                        acc[it][6] * r, acc[it][7] * r);
        }
    }
}

// ---------------- 7) DistMult ----------------
__global__ void distmult_kernel(const float* __restrict__ bias,
                                const float* __restrict__ rel_emb,
                                const void* __restrict__ si,
                                const void* __restrict__ ri,
                                const void* __restrict__ di,
                                float* __restrict__ out) {
    int wid  = (blockIdx.x * blockDim.x + threadIdx.x) >> 5;
    int lane = threadIdx.x & 31;
    if (wid >= BATCH) return;
    int s = load_idx(si, wid);
    int r = load_idx(ri, wid);
    int d = load_idx(di, wid);
    const float* ps = g_out + (size_t)s * HID;
    const float* pd = g_out + (size_t)d * HID;
    const float* pr = rel_emb + (size_t)r * HID;
    float acc = 0.f;
    for (int k = lane; k < HID; k += 32) {
        float b = bias[k];
        acc = fmaf((ps[k] + b) * pr[k], (pd[k] + b), acc);
    }
    acc = warp_reduce(acc);
    if (lane == 0) out[wid] = acc;
}

// ---------------- launch ----------------
extern "C" void kernel_launch(void* const* d_in, const int* in_sizes, int n_in,
                              void* d_out, int out_size) {
    const float* node_emb   = (const float*)d_in[0];
    const float* Wm         = (const float*)d_in[1];
    const float* bias       = (const float*)d_in[2];
    const float* a_src      = (const float*)d_in[3];
    const float* a_dst      = (const float*)d_in[4];
    const float* a_rel      = (const float*)d_in[5];
    const float* rel_feat   = (const float*)d_in[6];
    const float* rel_emb    = (const float*)d_in[7];
    const void*  edge_index = d_in[8];
    const void*  edge_type  = d_in[9];
    const void*  src_ids    = d_in[10];
    const void*  rel_ids    = d_in[11];
    const void*  dst_ids    = d_in[12];
    float* out = (float*)d_out;

    cudaFuncSetAttribute(gemm_mma_kernel,
                         cudaFuncAttributeMaxDynamicSharedMemorySize, SM_TOT);

    init_mark_cvec_kernel<<<INIT_BLOCKS + CVEC_BLOCKS, 256>>>(
        src_ids, dst_ids, Wm, a_src, a_dst, rel_feat, a_rel);
    mark_src_kernel<<<(E_EDGES + 255) / 256, 256>>>(edge_index);
    compact_kernel<<<(N_NODES + 255) / 256, 256>>>();
    split_fused_kernel<<<SPLITA_BLOCKS + SPLITB_BLOCKS + FILL_BLOCKS, 256>>>(
        node_emb, Wm, edge_index);

    dim3 ggrid(NT_N, NT_M);
    gemm_mma_kernel<<<ggrid, 256, SM_TOT>>>();

    agg_kernel<<<(MAX_OUT * 32 + 255) / 256, 256>>>(edge_index, edge_type);
    distmult_kernel<<<(BATCH * 32 + 255) / 256, 256>>>(bias, rel_emb,
                                                       src_ids, rel_ids, dst_ids, out);
}

// round 16
// speedup vs baseline: 1.2788x; 1.0388x over previous
#include <cuda_runtime.h>
#include <cuda_fp16.h>
#include <cfloat>
#include <cstdint>

#define N_NODES 50000
#define IN_DIM  1024
#define E_EDGES 100000
#define NUM_REL 40
#define HEADS   4
#define OUT_DIM 200
#define HID     800
#define BATCH   8192
#define NEG_SLOPE 0.2f

#define BM 128
#define BN 128
#define BK 32
#define NCHUNK (IN_DIM / BK)            // 32
#define NT_M ((N_NODES + BM - 1) / BM)
#define NT_N 7
#define PAD_N (NT_N * BN)               // 896

#define A_STRIDE 80
#define A_VER_SZ (128 * A_STRIDE)       // 10240
#define B_VER_SZ (128 * A_STRIDE)       // 10240
#define SA_OFF(buf) ((buf) * A_VER_SZ)
#define SB_OFF(buf) (3 * A_VER_SZ + (buf) * B_VER_SZ)
#define SM_TOT (3 * A_VER_SZ + 3 * B_VER_SZ)   // 61440

#define SPLITA_BLOCKS 592
#define SPLITB_BLOCKS ((IN_DIM / 32) * (PAD_N / 32))   // 896
#define FILL_BLOCKS  ((E_EDGES + 255) / 256)           // 391
#define INIT_BLOCKS  ((N_NODES * HEADS + 255) / 256)   // 782
#define CVEC_BLOCKS  (((IN_DIM + NUM_REL) * HEADS + 7) / 8)  // 532
#define MAX_OUT (2 * BATCH)

// ---------------- scratch (device globals) ----------------
__device__ __align__(16) __half g_h  [(size_t)N_NODES * HID];  // compacted h rows (fp16)
__device__ __align__(16) float g_out[(size_t)N_NODES * HID];   // node-indexed
__device__ __align__(16) __half g_Ah[(size_t)N_NODES * IN_DIM];
__device__ __align__(16) __half g_Bh[(size_t)PAD_N * IN_DIM];
__device__ __align__(16) float g_csrc[IN_DIM * HEADS];
__device__ __align__(16) float g_cdst[IN_DIM * HEADS];
__device__ __align__(16) float g_ssrc  [N_NODES * HEADS];
__device__ __align__(16) float g_sdst  [N_NODES * HEADS];
__device__ float g_rlog  [NUM_REL * HEADS];
__device__ int   g_cnt   [N_NODES];
__device__ int   g_rowptr[N_NODES];
__device__ int   g_cursor[N_NODES];
__device__ int   g_csre  [E_EDGES];
__device__ unsigned char g_need_out[N_NODES];   // monotone marks
__device__ unsigned char g_need_h  [N_NODES];
__device__ int   g_hidx  [N_NODES];
__device__ int   g_hlist [N_NODES];
__device__ int   g_ulist [N_NODES];
__device__ int   g_olist [MAX_OUT];
__device__ int   g_hcount;
__device__ int   g_ucount;
__device__ int   g_ocount;
__device__ int   g_ebase;
__device__ int   g_is64;

// ---------------- helpers ----------------
__device__ __forceinline__ int load_idx(const void* p, int i) {
    if (g_is64) return (int)((const long long*)p)[i];
    return ((const int*)p)[i];
}
__device__ __forceinline__ float warp_reduce(float v) {
    #pragma unroll
    for (int o = 16; o > 0; o >>= 1) v += __shfl_down_sync(0xffffffffu, v, o);
    return v;
}
__device__ __forceinline__ uint32_t smem_u32(const void* p) {
    uint32_t a;
    asm("{ .reg .u64 t; cvta.to.shared.u64 t, %1; cvt.u32.u64 %0, t; }" : "=r"(a) : "l"(p));
    return a;
}
__device__ __forceinline__ void cp_async16(uint32_t s, const void* g) {
    asm volatile("cp.async.cg.shared.global [%0], [%1], 16;" :: "r"(s), "l"(g));
}
__device__ __forceinline__ void cp_commit() {
    asm volatile("cp.async.commit_group;" ::: "memory");
}
template<int NN> __device__ __forceinline__ void cp_wait() {
    asm volatile("cp.async.wait_group %0;" :: "n"(NN) : "memory");
}
__device__ __forceinline__ void ldm_x4(uint32_t* r, uint32_t addr) {
    asm volatile("ldmatrix.sync.aligned.m8n8.x4.shared.b16 {%0,%1,%2,%3}, [%4];"
                 : "=r"(r[0]), "=r"(r[1]), "=r"(r[2]), "=r"(r[3]) : "r"(addr));
}
__device__ __forceinline__ void mma16816(float* d, const uint32_t* a, const uint32_t* b) {
    asm volatile(
        "mma.sync.aligned.m16n8k16.row.col.f32.f16.f16.f32 "
        "{%0,%1,%2,%3}, {%4,%5,%6,%7}, {%8,%9}, {%0,%1,%2,%3};"
        : "+f"(d[0]), "+f"(d[1]), "+f"(d[2]), "+f"(d[3])
        : "r"(a[0]), "r"(a[1]), "r"(a[2]), "r"(a[3]), "r"(b[0]), "r"(b[1]));
}

// ---------------- 1) init + dtype + mark endpoints + cvec/rel (merged) -------------
__global__ void init_mark_cvec_kernel(const void* __restrict__ si, const void* __restrict__ di,
                                      const float* __restrict__ Wm,
                                      const float* __restrict__ a_src,
                                      const float* __restrict__ a_dst,
                                      const float* __restrict__ rel_feat,
                                      const float* __restrict__ a_rel) {
    const int bid = blockIdx.x;
    const int t = threadIdx.x;
    if (bid < INIT_BLOCKS) {
        __shared__ int s_is64;
        const int tid = bid * 256 + t;
        if (t == 0) {
            const long long* p = (const long long*)si;
            int ok = 1;
            for (int i = 0; i < 64; i++) {
                long long v = p[i];
                if (v < 0 || v >= N_NODES) { ok = 0; break; }
            }
            s_is64 = ok;
            if (bid == 0) g_is64 = ok;
        }
        if (tid < N_NODES * HEADS) { g_ssrc[tid] = 0.0f; g_sdst[tid] = 0.0f; }
        if (tid < N_NODES) g_cnt[tid] = 0;
        if (tid == 0) { g_hcount = 0; g_ucount = 0; g_ocount = 0; g_ebase = 0; }
        __syncthreads();
        const int is64 = s_is64;
        if (tid < BATCH) {
            int n = is64 ? (int)((const long long*)si)[tid] : ((const int*)si)[tid];
            g_need_out[n] = 1;
        } else if (tid < 2 * BATCH) {
            int i = tid - BATCH;
            int n = is64 ? (int)((const long long*)di)[i] : ((const int*)di)[i];
            g_need_out[n] = 1;
        }
    } else {
        int gwid = (bid - INIT_BLOCKS) * 8 + (t >> 5);
        int lane = t & 31;
        if (gwid < IN_DIM * HEADS) {
            int k = gwid >> 2, h = gwid & 3;
            const float* wrow = Wm + (size_t)k * HID + h * OUT_DIM;
            const float* as = a_src + h * OUT_DIM;
            const float* ad = a_dst + h * OUT_DIM;
            float cs = 0.f, cd = 0.f;
            for (int d = lane; d < OUT_DIM; d += 32) {
                float w = wrow[d];
                cs = fmaf(w, as[d], cs);
                cd = fmaf(w, ad[d], cd);
            }
            cs = warp_reduce(cs);
            cd = warp_reduce(cd);
            if (lane == 0) { g_csrc[k * 4 + h] = cs; g_cdst[k * 4 + h] = cd; }
        } else if (gwid < (IN_DIM + NUM_REL) * HEADS) {
            int w2 = gwid - IN_DIM * HEADS;
            int r = w2 >> 2, h = w2 & 3;
            const float* rp = rel_feat + (size_t)r * HID + h * OUT_DIM;
            const float* ar = a_rel + h * OUT_DIM;
            float s = 0.f;
            for (int d = lane; d < OUT_DIM; d += 32) s = fmaf(rp[d], ar[d], s);
            s = warp_reduce(s);
            if (lane == 0) g_rlog[w2] = s;
        }
    }
}

// ---------------- 2) mark needed h rows + count gated in-edges ----------------
__global__ void mark_src_kernel(const void* __restrict__ ei) {
    int e = blockIdx.x * blockDim.x + threadIdx.x;
    if (e >= E_EDGES) return;
    int d = load_idx(ei, E_EDGES + e);
    if (g_need_out[d]) {
        int s = load_idx(ei, e);
        g_need_h[s] = 1;
        atomicAdd(&g_cnt[d], 1);
    }
}

// ---------------- 3) compact lists + allocate CSR segments ----------------
__global__ void compact_kernel() {
    int n = blockIdx.x * blockDim.x + threadIdx.x;
    if (n >= N_NODES) return;
    unsigned char nh = g_need_h[n];
    unsigned char no = g_need_out[n];
    if (nh) {
        int p = atomicAdd(&g_hcount, 1);
        g_hlist[p] = n;
        g_hidx[n] = p;
    }
    if (nh || no) {
        int p = atomicAdd(&g_ucount, 1);
        g_ulist[p] = n;
    }
    if (no) {
        int p = atomicAdd(&g_ocount, 1);
        g_olist[p] = n;
        int base = atomicAdd(&g_ebase, g_cnt[n]);
        g_rowptr[n] = base;
        g_cursor[n] = base;
    }
}

// ---------------- 4) s-pass (flag-gated) + W^T + CSR fill (merged) ----------------
__global__ void __launch_bounds__(256) split_fused_kernel(const float* __restrict__ A,
                                                          const float* __restrict__ Wm,
                                                          const void* __restrict__ ei) {
    const int bid = blockIdx.x;
    if (bid < SPLITA_BLOCKS) {
        const int t = threadIdx.x;
        const int lane = t & 31;
        const int ulen = g_ucount;
        float4 cs[4], cd[4];
        #pragma unroll
        for (int q = 0; q < 4; q++) {
            cs[q] = ((const float4*)g_csrc)[t * 4 + q];
            cd[q] = ((const float4*)g_cdst)[t * 4 + q];
        }
        for (int li = bid; li < ulen; li += SPLITA_BLOCKS) {
            const int n = g_ulist[li];
            const bool nh = g_need_h[n];      // uniform across block
            const bool no = g_need_out[n];
            float4 a = ((const float4*)(A + (size_t)n * IN_DIM))[t];
            float av[4] = {a.x, a.y, a.z, a.w};
            if (nh) {
                // fp16 store of A row (only edge sources feed the GEMM)
                __half2* ph = (__half2*)(g_Ah + (size_t)n * IN_DIM) + t * 2;
                ph[0] = __halves2half2(__float2half(a.x), __float2half(a.y));
                ph[1] = __halves2half2(__float2half(a.z), __float2half(a.w));
                float ss0 = 0.f, ss1 = 0.f, ss2 = 0.f, ss3 = 0.f;
                #pragma unroll
                for (int q = 0; q < 4; q++) {
                    ss0 = fmaf(av[q], cs[q].x, ss0); ss1 = fmaf(av[q], cs[q].y, ss1);
                    ss2 = fmaf(av[q], cs[q].z, ss2); ss3 = fmaf(av[q], cs[q].w, ss3);
                }
                #pragma unroll
                for (int o = 16; o > 0; o >>= 1) {
                    ss0 += __shfl_xor_sync(0xffffffffu, ss0, o);
                    ss1 += __shfl_xor_sync(0xffffffffu, ss1, o);
                    ss2 += __shfl_xor_sync(0xffffffffu, ss2, o);
                    ss3 += __shfl_xor_sync(0xffffffffu, ss3, o);
                }
                if (lane == 0) {
                    atomicAdd(&g_ssrc[n * 4 + 0], ss0);
                    atomicAdd(&g_ssrc[n * 4 + 1], ss1);
                    atomicAdd(&g_ssrc[n * 4 + 2], ss2);
                    atomicAdd(&g_ssrc[n * 4 + 3], ss3);
                }
            }
            if (no) {
                float sd0 = 0.f, sd1 = 0.f, sd2 = 0.f, sd3 = 0.f;
                #pragma unroll
                for (int q = 0; q < 4; q++) {
                    sd0 = fmaf(av[q], cd[q].x, sd0); sd1 = fmaf(av[q], cd[q].y, sd1);
                    sd2 = fmaf(av[q], cd[q].z, sd2); sd3 = fmaf(av[q], cd[q].w, sd3);
                }
                #pragma unroll
                for (int o = 16; o > 0; o >>= 1) {
                    sd0 += __shfl_xor_sync(0xffffffffu, sd0, o);
                    sd1 += __shfl_xor_sync(0xffffffffu, sd1, o);
                    sd2 += __shfl_xor_sync(0xffffffffu, sd2, o);
                    sd3 += __shfl_xor_sync(0xffffffffu, sd3, o);
                }
                if (lane == 0) {
                    atomicAdd(&g_sdst[n * 4 + 0], sd0);
                    atomicAdd(&g_sdst[n * 4 + 1], sd1);
                    atomicAdd(&g_sdst[n * 4 + 2], sd2);
                    atomicAdd(&g_sdst[n * 4 + 3], sd3);
                }
            }
        }
    } else if (bid < SPLITA_BLOCKS + SPLITB_BLOCKS) {
        __shared__ float tile[32][33];
        const int b = bid - SPLITA_BLOCKS;
        const int tx = threadIdx.x & 31;
        const int ty = threadIdx.x >> 5;
        const int k0 = (b % (IN_DIM / 32)) * 32;
        const int n0 = (b / (IN_DIM / 32)) * 32;
        #pragma unroll
        for (int j = 0; j < 4; j++) {
            int k = k0 + ty + j * 8;
            int n = n0 + tx;
            tile[ty + j * 8][tx] = (n < HID) ? Wm[(size_t)k * HID + n] : 0.0f;
        }
        __syncthreads();
        #pragma unroll
        for (int j = 0; j < 4; j++) {
            int n = n0 + ty + j * 8;
            int k = k0 + tx;
            g_Bh[(size_t)n * IN_DIM + k] = __float2half(tile[tx][ty + j * 8]);
        }
    } else {
        // CSR fill
        int e = (bid - SPLITA_BLOCKS - SPLITB_BLOCKS) * 256 + threadIdx.x;
        if (e < E_EDGES) {
            int d = load_idx(ei, E_EDGES + e);
            if (g_need_out[d]) {
                int pos = atomicAdd(&g_cursor[d], 1);
                g_csre[pos] = e;
            }
        }
    }
}

// ---------------- 5) HMMA GEMM: 3-stage pipeline, fp16 output ----------------
__global__ void __launch_bounds__(256) gemm_mma_kernel() {
    __shared__ int rowlist[BM];
    const int len = g_hcount;
    const int mt0 = blockIdx.y * BM;
    if (mt0 >= len) return;

    extern __shared__ char smem[];
    const uint32_t sbase = smem_u32(smem);
    const int t = threadIdx.x;
    const int lane = t & 31;
    const int warp = t >> 5;
    const int wm = warp >> 1;
    const int wn = warp & 1;
    const int n0 = blockIdx.x * BN;

    if (t < BM) {
        int rr = mt0 + t;
        rowlist[t] = g_hlist[rr < len ? rr : len - 1];
    }
    __syncthreads();

    float acc[2][8][4];
    #pragma unroll
    for (int mi = 0; mi < 2; mi++)
        #pragma unroll
        for (int nj = 0; nj < 8; nj++)
            #pragma unroll
            for (int q = 0; q < 4; q++) acc[mi][nj][q] = 0.0f;

    auto load_chunk = [&](int c, int buf) {
        #pragma unroll
        for (int i = 0; i < 2; i++) {
            int lin = i * 256 + t;
            int r = lin >> 2, seg = lin & 3;
            int node = rowlist[r];
            size_t go = (size_t)node * IN_DIM + c * BK + seg * 8;
            uint32_t so = (uint32_t)(r * A_STRIDE + seg * 16);
            cp_async16(sbase + SA_OFF(buf) + so, g_Ah + go);
        }
        #pragma unroll
        for (int i = 0; i < 2; i++) {
            int lin = i * 256 + t;
            int r = lin >> 2, seg = lin & 3;
            size_t go = (size_t)(n0 + r) * IN_DIM + c * BK + seg * 8;
            uint32_t so = (uint32_t)(r * A_STRIDE + seg * 16);
            cp_async16(sbase + SB_OFF(buf) + so, g_Bh + go);
        }
        cp_commit();
    };

    load_chunk(0, 0);
    load_chunk(1, 1);

    for (int c = 0; c < NCHUNK; c++) {
        if (c == NCHUNK - 1) cp_wait<0>(); else cp_wait<1>();
        __syncthreads();
        if (c + 2 < NCHUNK) load_chunk(c + 2, (c + 2) % 3);
        const int buf = c % 3;

        #pragma unroll
        for (int k16 = 0; k16 < BK; k16 += 16) {
            uint32_t af[2][4];
            #pragma unroll
            for (int mi = 0; mi < 2; mi++) {
                int r = wm * 32 + mi * 16 + (lane & 7) + ((lane >> 3) & 1) * 8;
                int colB = (k16 + (lane >> 4) * 8) * 2;
                ldm_x4(af[mi], sbase + SA_OFF(buf) + r * A_STRIDE + colB);
            }
            uint32_t bf[8][2];
            #pragma unroll
            for (int pr = 0; pr < 4; pr++) {
                uint32_t r4[4];
                int n = wn * 64 + pr * 16 + ((lane >> 4) & 1) * 8 + (lane & 7);
                int colB = (k16 + ((lane >> 3) & 1) * 8) * 2;
                ldm_x4(r4, sbase + SB_OFF(buf) + n * A_STRIDE + colB);
                bf[pr * 2 + 0][0] = r4[0]; bf[pr * 2 + 0][1] = r4[1];
                bf[pr * 2 + 1][0] = r4[2]; bf[pr * 2 + 1][1] = r4[3];
            }
            #pragma unroll
            for (int mi = 0; mi < 2; mi++)
                #pragma unroll
                for (int nj = 0; nj < 8; nj++)
                    mma16816(acc[mi][nj], af[mi], bf[nj]);
        }
    }

    #pragma unroll
    for (int mi = 0; mi < 2; mi++)
        #pragma unroll
        for (int nj = 0; nj < 8; nj++) {
            int tileN = n0 + wn * 64 + nj * 8;
            if (tileN >= HID) continue;
            int col = tileN + 2 * (lane & 3);
            int lr0 = wm * 32 + mi * 16 + (lane >> 2);
            if (mt0 + lr0 < len)
                *(__half2*)(g_h + (size_t)(mt0 + lr0) * HID + col) =
                    __floats2half2_rn(acc[mi][nj][0], acc[mi][nj][1]);
            if (mt0 + lr0 + 8 < len)
                *(__half2*)(g_h + (size_t)(mt0 + lr0 + 8) * HID + col) =
                    __floats2half2_rn(acc[mi][nj][2], acc[mi][nj][3]);
        }
}

// ---------------- 6) fused softmax + aggregate (single edge pass, fp16 h) ----------
__global__ void __launch_bounds__(256) agg_kernel(const void* __restrict__ ei,
                                                  const void* __restrict__ et) {
    int o    = (blockIdx.x * blockDim.x + threadIdx.x) >> 5;
    int lane = threadIdx.x & 31;
    if (o >= g_ocount) return;
    int n = g_olist[o];
    int rp0 = g_rowptr[n];
    int rp1 = rp0 + g_cnt[n];

    float acc[4][8];
    #pragma unroll
    for (int it = 0; it < 4; it++)
        #pragma unroll
        for (int q = 0; q < 8; q++) acc[it][q] = 0.0f;
    float dn0 = 0.f, dn1 = 0.f, dn2 = 0.f, dn3 = 0.f;

    for (int j = rp0; j < rp1; j++) {
        int e = g_csre[j];
        int s = load_idx(ei, e);
        float ev_l = 0.f;
        if (lane < 4) {
            int r = load_idx(et, e);
            float x = g_ssrc[s * 4 + lane] + g_sdst[n * 4 + lane] + g_rlog[r * 4 + lane];
            x = (x >= 0.f) ? x : NEG_SLOPE * x;
            ev_l = expf(x);
        }
        float e0 = __shfl_sync(0xffffffffu, ev_l, 0);
        float e1 = __shfl_sync(0xffffffffu, ev_l, 1);
        float e2 = __shfl_sync(0xffffffffu, ev_l, 2);
        float e3 = __shfl_sync(0xffffffffu, ev_l, 3);
        dn0 += e0; dn1 += e1; dn2 += e2; dn3 += e3;
        int hrow = g_hidx[s];
        const uint4* hp = (const uint4*)(g_h + (size_t)hrow * HID);
        #pragma unroll
        for (int it = 0; it < 4; it++) {
            int c = lane + it * 32;
            if (c < 100) {
                float a = (c < 25) ? e0 : (c < 50) ? e1 : (c < 75) ? e2 : e3;
                uint4 v = hp[c];
                float2 f0 = __half22float2(*(const __half2*)&v.x);
                float2 f1 = __half22float2(*(const __half2*)&v.y);
                float2 f2 = __half22float2(*(const __half2*)&v.z);
                float2 f3 = __half22float2(*(const __half2*)&v.w);
                acc[it][0] = fmaf(a, f0.x, acc[it][0]);
                acc[it][1] = fmaf(a, f0.y, acc[it][1]);
                acc[it][2] = fmaf(a, f1.x, acc[it][2]);
                acc[it][3] = fmaf(a, f1.y, acc[it][3]);
                acc[it][4] = fmaf(a, f2.x, acc[it][4]);
                acc[it][5] = fmaf(a, f2.y, acc[it][5]);
                acc[it][6] = fmaf(a, f3.x, acc[it][6]);
                acc[it][7] = fmaf(a, f3.y, acc[it][7]);
            }
        }
    }
    float r0 = (dn0 > 0.f) ? 1.0f / dn0 : 0.0f;
    float r1 = (dn1 > 0.f) ? 1.0f / dn1 : 0.0f;
    float r2 = (dn2 > 0.f) ? 1.0f / dn2 : 0.0f;
    float r3 = (dn3 > 0.f) ? 1.0f / dn3 : 0.0f;
    float4* op = (float4*)(g_out + (size_t)n * HID);
    #pragma unroll
    for (int it = 0; it < 4; it++) {
        int c = lane + it * 32;
        if (c < 100) {
            float r = (c < 25) ? r0 : (c < 50) ? r1 : (c < 75) ? r2 : r3;
            op[c * 2]     = make_float4(acc[it][0] * r, acc[it][1] * r,
                                        acc[it][2] * r, acc[it][3] * r);
            op[c * 2 + 1] = make_float4(acc[it][4] * r, acc[it][5] * r,
                                        acc[it][6] * r, acc[it][7] * r);
        }
    }
}

// ---------------- 7) DistMult ----------------
__global__ void distmult_kernel(const float* __restrict__ bias,
                                const float* __restrict__ rel_emb,
                                const void* __restrict__ si,
                                const void* __restrict__ ri,
                                const void* __restrict__ di,
                                float* __restrict__ out) {
    int wid  = (blockIdx.x * blockDim.x + threadIdx.x) >> 5;
    int lane = threadIdx.x & 31;
    if (wid >= BATCH) return;
    int s = load_idx(si, wid);
    int r = load_idx(ri, wid);
    int d = load_idx(di, wid);
    const float* ps = g_out + (size_t)s * HID;
    const float* pd = g_out + (size_t)d * HID;
    const float* pr = rel_emb + (size_t)r * HID;
    float acc = 0.f;
    for (int k = lane; k < HID; k += 32) {
        float b = bias[k];
        acc = fmaf((ps[k] + b) * pr[k], (pd[k] + b), acc);
    }
    acc = warp_reduce(acc);
    if (lane == 0) out[wid] = acc;
}

// ---------------- launch ----------------
extern "C" void kernel_launch(void* const* d_in, const int* in_sizes, int n_in,
                              void* d_out, int out_size) {
    const float* node_emb   = (const float*)d_in[0];
    const float* Wm         = (const float*)d_in[1];
    const float* bias       = (const float*)d_in[2];
    const float* a_src      = (const float*)d_in[3];
    const float* a_dst      = (const float*)d_in[4];
    const float* a_rel      = (const float*)d_in[5];
    const float* rel_feat   = (const float*)d_in[6];
    const float* rel_emb    = (const float*)d_in[7];
    const void*  edge_index = d_in[8];
    const void*  edge_type  = d_in[9];
    const void*  src_ids    = d_in[10];
    const void*  rel_ids    = d_in[11];
    const void*  dst_ids    = d_in[12];
    float* out = (float*)d_out;

    cudaFuncSetAttribute(gemm_mma_kernel,
                         cudaFuncAttributeMaxDynamicSharedMemorySize, SM_TOT);

    init_mark_cvec_kernel<<<INIT_BLOCKS + CVEC_BLOCKS, 256>>>(
        src_ids, dst_ids, Wm, a_src, a_dst, rel_feat, a_rel);
    mark_src_kernel<<<(E_EDGES + 255) / 256, 256>>>(edge_index);
    compact_kernel<<<(N_NODES + 255) / 256, 256>>>();
    split_fused_kernel<<<SPLITA_BLOCKS + SPLITB_BLOCKS + FILL_BLOCKS, 256>>>(
        node_emb, Wm, edge_index);

    dim3 ggrid(NT_N, NT_M);
    gemm_mma_kernel<<<ggrid, 256, SM_TOT>>>();

    agg_kernel<<<(MAX_OUT * 32 + 255) / 256, 256>>>(edge_index, edge_type);
    distmult_kernel<<<(BATCH * 32 + 255) / 256, 256>>>(bias, rel_emb,
                                                       src_ids, rel_ids, dst_ids, out);
}

// round 17
// speedup vs baseline: 1.2875x; 1.0068x over previous
#include <cuda_runtime.h>
#include <cuda_fp16.h>
#include <cfloat>
#include <cstdint>

#define N_NODES 50000
#define IN_DIM  1024
#define E_EDGES 100000
#define NUM_REL 40
#define HEADS   4
#define OUT_DIM 200
#define HID     800
#define BATCH   8192
#define NEG_SLOPE 0.2f

#define BM 128
#define BN 128
#define BK 32
#define NCHUNK (IN_DIM / BK)            // 32
#define NT_M ((N_NODES + BM - 1) / BM)
#define NT_N 7
#define PAD_N (NT_N * BN)               // 896

#define A_STRIDE 80
#define A_VER_SZ (128 * A_STRIDE)       // 10240
#define B_VER_SZ (128 * A_STRIDE)       // 10240
#define SA_OFF(buf) ((buf) * A_VER_SZ)
#define SB_OFF(buf) (3 * A_VER_SZ + (buf) * B_VER_SZ)
#define SM_TOT (3 * A_VER_SZ + 3 * B_VER_SZ)   // 61440

#define SPLITA_BLOCKS 592
#define SPLITB_BLOCKS ((IN_DIM / 32) * (PAD_N / 32))   // 896
#define FILL_BLOCKS  ((E_EDGES + 255) / 256)           // 391
#define INIT_BLOCKS  ((N_NODES * HEADS + 255) / 256)   // 782
#define CVEC_BLOCKS  (((IN_DIM + NUM_REL) * HEADS + 7) / 8)  // 532
#define MAX_OUT (2 * BATCH)

// ---------------- scratch (device globals) ----------------
__device__ __align__(16) __half g_h  [(size_t)N_NODES * HID];  // compacted h rows (fp16)
__device__ __align__(16) float g_out[(size_t)N_NODES * HID];   // node-indexed
__device__ __align__(16) __half g_Ah[(size_t)N_NODES * IN_DIM];
__device__ __align__(16) __half g_Bh[(size_t)PAD_N * IN_DIM];
__device__ __align__(16) float g_csrc[IN_DIM * HEADS];
__device__ __align__(16) float g_cdst[IN_DIM * HEADS];
__device__ __align__(16) float g_ssrc  [N_NODES * HEADS];
__device__ __align__(16) float g_sdst  [N_NODES * HEADS];
__device__ float g_rlog  [NUM_REL * HEADS];
__device__ int   g_cnt   [N_NODES];
__device__ int   g_rowptr[N_NODES];
__device__ int   g_cursor[N_NODES];
__device__ int   g_csre  [E_EDGES];
__device__ unsigned char g_need_out[N_NODES];   // monotone marks
__device__ unsigned char g_need_h  [N_NODES];
__device__ int   g_hidx  [N_NODES];
__device__ int   g_hlist [N_NODES];
__device__ int   g_ulist [N_NODES];
__device__ int   g_olist [MAX_OUT];
__device__ int   g_hcount;
__device__ int   g_ucount;
__device__ int   g_ocount;
__device__ int   g_ebase;
__device__ int   g_is64;

// ---------------- helpers ----------------
__device__ __forceinline__ int load_idx(const void* p, int i) {
    if (g_is64) return (int)((const long long*)p)[i];
    return ((const int*)p)[i];
}
__device__ __forceinline__ float warp_reduce(float v) {
    #pragma unroll
    for (int o = 16; o > 0; o >>= 1) v += __shfl_down_sync(0xffffffffu, v, o);
    return v;
}
// Interleaved 4-value warp reduction: returns head (lane&3)'s total in lane;
// lanes 0..3 hold heads 0..3 complete sums. 6 shuffles total.
__device__ __forceinline__ float reduce4(float v0, float v1, float v2, float v3, int lane) {
    float ps = (lane & 1) ? v1 : v0;
    float qs = (lane & 1) ? v0 : v1;
    ps += __shfl_xor_sync(0xffffffffu, qs, 1);
    float pt = (lane & 1) ? v3 : v2;
    float qt = (lane & 1) ? v2 : v3;
    pt += __shfl_xor_sync(0xffffffffu, qt, 1);
    float u = (lane & 2) ? pt : ps;
    float w = (lane & 2) ? ps : pt;
    u += __shfl_xor_sync(0xffffffffu, w, 2);
    u += __shfl_xor_sync(0xffffffffu, u, 4);
    u += __shfl_xor_sync(0xffffffffu, u, 8);
    u += __shfl_xor_sync(0xffffffffu, u, 16);
    return u;
}
__device__ __forceinline__ uint32_t smem_u32(const void* p) {
    uint32_t a;
    asm("{ .reg .u64 t; cvta.to.shared.u64 t, %1; cvt.u32.u64 %0, t; }" : "=r"(a) : "l"(p));
    return a;
}
__device__ __forceinline__ void cp_async16(uint32_t s, const void* g) {
    asm volatile("cp.async.cg.shared.global [%0], [%1], 16;" :: "r"(s), "l"(g));
}
__device__ __forceinline__ void cp_commit() {
    asm volatile("cp.async.commit_group;" ::: "memory");
}
template<int NN> __device__ __forceinline__ void cp_wait() {
    asm volatile("cp.async.wait_group %0;" :: "n"(NN) : "memory");
}
__device__ __forceinline__ void ldm_x4(uint32_t* r, uint32_t addr) {
    asm volatile("ldmatrix.sync.aligned.m8n8.x4.shared.b16 {%0,%1,%2,%3}, [%4];"
                 : "=r"(r[0]), "=r"(r[1]), "=r"(r[2]), "=r"(r[3]) : "r"(addr));
}
__device__ __forceinline__ void mma16816(float* d, const uint32_t* a, const uint32_t* b) {
    asm volatile(
        "mma.sync.aligned.m16n8k16.row.col.f32.f16.f16.f32 "
        "{%0,%1,%2,%3}, {%4,%5,%6,%7}, {%8,%9}, {%0,%1,%2,%3};"
        : "+f"(d[0]), "+f"(d[1]), "+f"(d[2]), "+f"(d[3])
        : "r"(a[0]), "r"(a[1]), "r"(a[2]), "r"(a[3]), "r"(b[0]), "r"(b[1]));
}

// ---------------- 1) init + dtype + mark endpoints + cvec/rel (merged) -------------
__global__ void init_mark_cvec_kernel(const void* __restrict__ si, const void* __restrict__ di,
                                      const float* __restrict__ Wm,
                                      const float* __restrict__ a_src,
                                      const float* __restrict__ a_dst,
                                      const float* __restrict__ rel_feat,
                                      const float* __restrict__ a_rel) {
    const int bid = blockIdx.x;
    const int t = threadIdx.x;
    if (bid < INIT_BLOCKS) {
        __shared__ int s_is64;
        const int tid = bid * 256 + t;
        if (t == 0) {
            const long long* p = (const long long*)si;
            int ok = 1;
            for (int i = 0; i < 64; i++) {
                long long v = p[i];
                if (v < 0 || v >= N_NODES) { ok = 0; break; }
            }
            s_is64 = ok;
            if (bid == 0) g_is64 = ok;
        }
        if (tid < N_NODES * HEADS) { g_ssrc[tid] = 0.0f; g_sdst[tid] = 0.0f; }
        if (tid < N_NODES) g_cnt[tid] = 0;
        if (tid == 0) { g_hcount = 0; g_ucount = 0; g_ocount = 0; g_ebase = 0; }
        __syncthreads();
        const int is64 = s_is64;
        if (tid < BATCH) {
            int n = is64 ? (int)((const long long*)si)[tid] : ((const int*)si)[tid];
            g_need_out[n] = 1;
        } else if (tid < 2 * BATCH) {
            int i = tid - BATCH;
            int n = is64 ? (int)((const long long*)di)[i] : ((const int*)di)[i];
            g_need_out[n] = 1;
        }
    } else {
        int gwid = (bid - INIT_BLOCKS) * 8 + (t >> 5);
        int lane = t & 31;
        if (gwid < IN_DIM * HEADS) {
            int k = gwid >> 2, h = gwid & 3;
            const float* wrow = Wm + (size_t)k * HID + h * OUT_DIM;
            const float* as = a_src + h * OUT_DIM;
            const float* ad = a_dst + h * OUT_DIM;
            float cs = 0.f, cd = 0.f;
            for (int d = lane; d < OUT_DIM; d += 32) {
                float w = wrow[d];
                cs = fmaf(w, as[d], cs);
                cd = fmaf(w, ad[d], cd);
            }
            cs = warp_reduce(cs);
            cd = warp_reduce(cd);
            if (lane == 0) { g_csrc[k * 4 + h] = cs; g_cdst[k * 4 + h] = cd; }
        } else if (gwid < (IN_DIM + NUM_REL) * HEADS) {
            int w2 = gwid - IN_DIM * HEADS;
            int r = w2 >> 2, h = w2 & 3;
            const float* rp = rel_feat + (size_t)r * HID + h * OUT_DIM;
            const float* ar = a_rel + h * OUT_DIM;
            float s = 0.f;
            for (int d = lane; d < OUT_DIM; d += 32) s = fmaf(rp[d], ar[d], s);
            s = warp_reduce(s);
            if (lane == 0) g_rlog[w2] = s;
        }
    }
}

// ---------------- 2) mark needed h rows + count gated in-edges ----------------
__global__ void mark_src_kernel(const void* __restrict__ ei) {
    int e = blockIdx.x * blockDim.x + threadIdx.x;
    if (e >= E_EDGES) return;
    int d = load_idx(ei, E_EDGES + e);
    if (g_need_out[d]) {
        int s = load_idx(ei, e);
        g_need_h[s] = 1;
        atomicAdd(&g_cnt[d], 1);
    }
}

// ---------------- 3) compact lists + allocate CSR segments ----------------
__global__ void compact_kernel() {
    int n = blockIdx.x * blockDim.x + threadIdx.x;
    if (n >= N_NODES) return;
    unsigned char nh = g_need_h[n];
    unsigned char no = g_need_out[n];
    if (nh) {
        int p = atomicAdd(&g_hcount, 1);
        g_hlist[p] = n;
        g_hidx[n] = p;
    }
    if (nh || no) {
        int p = atomicAdd(&g_ucount, 1);
        g_ulist[p] = n;
    }
    if (no) {
        int p = atomicAdd(&g_ocount, 1);
        g_olist[p] = n;
        int base = atomicAdd(&g_ebase, g_cnt[n]);
        g_rowptr[n] = base;
        g_cursor[n] = base;
    }
}

// ---------------- 4) s-pass (flag-gated, fast reduce) + W^T + CSR fill ------------
__global__ void __launch_bounds__(256) split_fused_kernel(const float* __restrict__ A,
                                                          const float* __restrict__ Wm,
                                                          const void* __restrict__ ei) {
    const int bid = blockIdx.x;
    if (bid < SPLITA_BLOCKS) {
        const int t = threadIdx.x;
        const int lane = t & 31;
        const int ulen = g_ucount;
        float4 cs[4], cd[4];
        #pragma unroll
        for (int q = 0; q < 4; q++) {
            cs[q] = ((const float4*)g_csrc)[t * 4 + q];
            cd[q] = ((const float4*)g_cdst)[t * 4 + q];
        }
        for (int li = bid; li < ulen; li += SPLITA_BLOCKS) {
            const int n = g_ulist[li];
            const bool nh = g_need_h[n];      // uniform across block
            const bool no = g_need_out[n];
            float4 a = ((const float4*)(A + (size_t)n * IN_DIM))[t];
            float av[4] = {a.x, a.y, a.z, a.w};
            if (nh) {
                __half2* ph = (__half2*)(g_Ah + (size_t)n * IN_DIM) + t * 2;
                ph[0] = __halves2half2(__float2half(a.x), __float2half(a.y));
                ph[1] = __halves2half2(__float2half(a.z), __float2half(a.w));
                float ss0 = 0.f, ss1 = 0.f, ss2 = 0.f, ss3 = 0.f;
                #pragma unroll
                for (int q = 0; q < 4; q++) {
                    ss0 = fmaf(av[q], cs[q].x, ss0); ss1 = fmaf(av[q], cs[q].y, ss1);
                    ss2 = fmaf(av[q], cs[q].z, ss2); ss3 = fmaf(av[q], cs[q].w, ss3);
                }
                float u = reduce4(ss0, ss1, ss2, ss3, lane);
                if (lane < 4) atomicAdd(&g_ssrc[n * 4 + lane], u);
            }
            if (no) {
                float sd0 = 0.f, sd1 = 0.f, sd2 = 0.f, sd3 = 0.f;
                #pragma unroll
                for (int q = 0; q < 4; q++) {
                    sd0 = fmaf(av[q], cd[q].x, sd0); sd1 = fmaf(av[q], cd[q].y, sd1);
                    sd2 = fmaf(av[q], cd[q].z, sd2); sd3 = fmaf(av[q], cd[q].w, sd3);
                }
                float u = reduce4(sd0, sd1, sd2, sd3, lane);
                if (lane < 4) atomicAdd(&g_sdst[n * 4 + lane], u);
            }
        }
    } else if (bid < SPLITA_BLOCKS + SPLITB_BLOCKS) {
        __shared__ float tile[32][33];
        const int b = bid - SPLITA_BLOCKS;
        const int tx = threadIdx.x & 31;
        const int ty = threadIdx.x >> 5;
        const int k0 = (b % (IN_DIM / 32)) * 32;
        const int n0 = (b / (IN_DIM / 32)) * 32;
        #pragma unroll
        for (int j = 0; j < 4; j++) {
            int k = k0 + ty + j * 8;
            int n = n0 + tx;
            tile[ty + j * 8][tx] = (n < HID) ? Wm[(size_t)k * HID + n] : 0.0f;
        }
        __syncthreads();
        #pragma unroll
        for (int j = 0; j < 4; j++) {
            int n = n0 + ty + j * 8;
            int k = k0 + tx;
            g_Bh[(size_t)n * IN_DIM + k] = __float2half(tile[tx][ty + j * 8]);
        }
    } else {
        // CSR fill
        int e = (bid - SPLITA_BLOCKS - SPLITB_BLOCKS) * 256 + threadIdx.x;
        if (e < E_EDGES) {
            int d = load_idx(ei, E_EDGES + e);
            if (g_need_out[d]) {
                int pos = atomicAdd(&g_cursor[d], 1);
                g_csre[pos] = e;
            }
        }
    }
}

// ---------------- 5) HMMA GEMM: 3-stage pipeline, fp16 output ----------------
__global__ void __launch_bounds__(256) gemm_mma_kernel() {
    __shared__ int rowlist[BM];
    const int len = g_hcount;
    const int mt0 = blockIdx.y * BM;
    if (mt0 >= len) return;

    extern __shared__ char smem[];
    const uint32_t sbase = smem_u32(smem);
    const int t = threadIdx.x;
    const int lane = t & 31;
    const int warp = t >> 5;
    const int wm = warp >> 1;
    const int wn = warp & 1;
    const int n0 = blockIdx.x * BN;

    if (t < BM) {
        int rr = mt0 + t;
        rowlist[t] = g_hlist[rr < len ? rr : len - 1];
    }
    __syncthreads();

    float acc[2][8][4];
    #pragma unroll
    for (int mi = 0; mi < 2; mi++)
        #pragma unroll
        for (int nj = 0; nj < 8; nj++)
            #pragma unroll
            for (int q = 0; q < 4; q++) acc[mi][nj][q] = 0.0f;

    auto load_chunk = [&](int c, int buf) {
        #pragma unroll
        for (int i = 0; i < 2; i++) {
            int lin = i * 256 + t;
            int r = lin >> 2, seg = lin & 3;
            int node = rowlist[r];
            size_t go = (size_t)node * IN_DIM + c * BK + seg * 8;
            uint32_t so = (uint32_t)(r * A_STRIDE + seg * 16);
            cp_async16(sbase + SA_OFF(buf) + so, g_Ah + go);
        }
        #pragma unroll
        for (int i = 0; i < 2; i++) {
            int lin = i * 256 + t;
            int r = lin >> 2, seg = lin & 3;
            size_t go = (size_t)(n0 + r) * IN_DIM + c * BK + seg * 8;
            uint32_t so = (uint32_t)(r * A_STRIDE + seg * 16);
            cp_async16(sbase + SB_OFF(buf) + so, g_Bh + go);
        }
        cp_commit();
    };

    load_chunk(0, 0);
    load_chunk(1, 1);

    for (int c = 0; c < NCHUNK; c++) {
        if (c == NCHUNK - 1) cp_wait<0>(); else cp_wait<1>();
        __syncthreads();
        if (c + 2 < NCHUNK) load_chunk(c + 2, (c + 2) % 3);
        const int buf = c % 3;

        #pragma unroll
        for (int k16 = 0; k16 < BK; k16 += 16) {
            uint32_t af[2][4];
            #pragma unroll
            for (int mi = 0; mi < 2; mi++) {
                int r = wm * 32 + mi * 16 + (lane & 7) + ((lane >> 3) & 1) * 8;
                int colB = (k16 + (lane >> 4) * 8) * 2;
                ldm_x4(af[mi], sbase + SA_OFF(buf) + r * A_STRIDE + colB);
            }
            uint32_t bf[8][2];
            #pragma unroll
            for (int pr = 0; pr < 4; pr++) {
                uint32_t r4[4];
                int n = wn * 64 + pr * 16 + ((lane >> 4) & 1) * 8 + (lane & 7);
                int colB = (k16 + ((lane >> 3) & 1) * 8) * 2;
                ldm_x4(r4, sbase + SB_OFF(buf) + n * A_STRIDE + colB);
                bf[pr * 2 + 0][0] = r4[0]; bf[pr * 2 + 0][1] = r4[1];
                bf[pr * 2 + 1][0] = r4[2]; bf[pr * 2 + 1][1] = r4[3];
            }
            #pragma unroll
            for (int mi = 0; mi < 2; mi++)
                #pragma unroll
                for (int nj = 0; nj < 8; nj++)
                    mma16816(acc[mi][nj], af[mi], bf[nj]);
        }
    }

    #pragma unroll
    for (int mi = 0; mi < 2; mi++)
        #pragma unroll
        for (int nj = 0; nj < 8; nj++) {
            int tileN = n0 + wn * 64 + nj * 8;
            if (tileN >= HID) continue;
            int col = tileN + 2 * (lane & 3);
            int lr0 = wm * 32 + mi * 16 + (lane >> 2);
            if (mt0 + lr0 < len)
                *(__half2*)(g_h + (size_t)(mt0 + lr0) * HID + col) =
                    __floats2half2_rn(acc[mi][nj][0], acc[mi][nj][1]);
            if (mt0 + lr0 + 8 < len)
                *(__half2*)(g_h + (size_t)(mt0 + lr0 + 8) * HID + col) =
                    __floats2half2_rn(acc[mi][nj][2], acc[mi][nj][3]);
        }
}

// ---------------- 6) fused softmax + aggregate (single edge pass, fp16 h) ----------
__global__ void __launch_bounds__(256) agg_kernel(const void* __restrict__ ei,
                                                  const void* __restrict__ et) {
    int o    = (blockIdx.x * blockDim.x + threadIdx.x) >> 5;
    int lane = threadIdx.x & 31;
    if (o >= g_ocount) return;
    int n = g_olist[o];
    int rp0 = g_rowptr[n];
    int rp1 = rp0 + g_cnt[n];

    float acc[4][8];
    #pragma unroll
    for (int it = 0; it < 4; it++)
        #pragma unroll
        for (int q = 0; q < 8; q++) acc[it][q] = 0.0f;
    float dn0 = 0.f, dn1 = 0.f, dn2 = 0.f, dn3 = 0.f;

    for (int j = rp0; j < rp1; j++) {
        int e = g_csre[j];
        int s = load_idx(ei, e);
        float ev_l = 0.f;
        if (lane < 4) {
            int r = load_idx(et, e);
            float x = g_ssrc[s * 4 + lane] + g_sdst[n * 4 + lane] + g_rlog[r * 4 + lane];
            x = (x >= 0.f) ? x : NEG_SLOPE * x;
            ev_l = expf(x);
        }
        float e0 = __shfl_sync(0xffffffffu, ev_l, 0);
        float e1 = __shfl_sync(0xffffffffu, ev_l, 1);
        float e2 = __shfl_sync(0xffffffffu, ev_l, 2);
        float e3 = __shfl_sync(0xffffffffu, ev_l, 3);
        dn0 += e0; dn1 += e1; dn2 += e2; dn3 += e3;
        int hrow = g_hidx[s];
        const uint4* hp = (const uint4*)(g_h + (size_t)hrow * HID);
        #pragma unroll
        for (int it = 0; it < 4; it++) {
            int c = lane + it * 32;
            if (c < 100) {
                float a = (c < 25) ? e0 : (c < 50) ? e1 : (c < 75) ? e2 : e3;
                uint4 v = hp[c];
                float2 f0 = __half22float2(*(const __half2*)&v.x);
                float2 f1 = __half22float2(*(const __half2*)&v.y);
                float2 f2 = __half22float2(*(const __half2*)&v.z);
                float2 f3 = __half22float2(*(const __half2*)&v.w);
                acc[it][0] = fmaf(a, f0.x, acc[it][0]);
                acc[it][1] = fmaf(a, f0.y, acc[it][1]);
                acc[it][2] = fmaf(a, f1.x, acc[it][2]);
                acc[it][3] = fmaf(a, f1.y, acc[it][3]);
                acc[it][4] = fmaf(a, f2.x, acc[it][4]);
                acc[it][5] = fmaf(a, f2.y, acc[it][5]);
                acc[it][6] = fmaf(a, f3.x, acc[it][6]);
                acc[it][7] = fmaf(a, f3.y, acc[it][7]);
            }
        }
    }
    float r0 = (dn0 > 0.f) ? 1.0f / dn0 : 0.0f;
    float r1 = (dn1 > 0.f) ? 1.0f / dn1 : 0.0f;
    float r2 = (dn2 > 0.f) ? 1.0f / dn2 : 0.0f;
    float r3 = (dn3 > 0.f) ? 1.0f / dn3 : 0.0f;
    float4* op = (float4*)(g_out + (size_t)n * HID);
    #pragma unroll
    for (int it = 0; it < 4; it++) {
        int c = lane + it * 32;
        if (c < 100) {
            float r = (c < 25) ? r0 : (c < 50) ? r1 : (c < 75) ? r2 : r3;
            op[c * 2]     = make_float4(acc[it][0] * r, acc[it][1] * r,
                                        acc[it][2] * r, acc[it][3] * r);
            op[c * 2 + 1] = make_float4(acc[it][4] * r, acc[it][5] * r,
                                        acc[it][6] * r, acc[it][7] * r);
        }
    }
}

// ---------------- 7) DistMult ----------------
__global__ void distmult_kernel(const float* __restrict__ bias,
                                const float* __restrict__ rel_emb,
                                const void* __restrict__ si,
                                const void* __restrict__ ri,
                                const void* __restrict__ di,
                                float* __restrict__ out) {
    int wid  = (blockIdx.x * blockDim.x + threadIdx.x) >> 5;
    int lane = threadIdx.x & 31;
    if (wid >= BATCH) return;
    int s = load_idx(si, wid);
    int r = load_idx(ri, wid);
    int d = load_idx(di, wid);
    const float* ps = g_out + (size_t)s * HID;
    const float* pd = g_out + (size_t)d * HID;
    const float* pr = rel_emb + (size_t)r * HID;
    float acc = 0.f;
    for (int k = lane; k < HID; k += 32) {
        float b = bias[k];
        acc = fmaf((ps[k] + b) * pr[k], (pd[k] + b), acc);
    }
    acc = warp_reduce(acc);
    if (lane == 0) out[wid] = acc;
}

// ---------------- launch ----------------
extern "C" void kernel_launch(void* const* d_in, const int* in_sizes, int n_in,
                              void* d_out, int out_size) {
    const float* node_emb   = (const float*)d_in[0];
    const float* Wm         = (const float*)d_in[1];
    const float* bias       = (const float*)d_in[2];
    const float* a_src      = (const float*)d_in[3];
    const float* a_dst      = (const float*)d_in[4];
    const float* a_rel      = (const float*)d_in[5];
    const float* rel_feat   = (const float*)d_in[6];
    const float* rel_emb    = (const float*)d_in[7];
    const void*  edge_index = d_in[8];
    const void*  edge_type  = d_in[9];
    const void*  src_ids    = d_in[10];
    const void*  rel_ids    = d_in[11];
    const void*  dst_ids    = d_in[12];
    float* out = (float*)d_out;

    cudaFuncSetAttribute(gemm_mma_kernel,
                         cudaFuncAttributeMaxDynamicSharedMemorySize, SM_TOT);

    init_mark_cvec_kernel<<<INIT_BLOCKS + CVEC_BLOCKS, 256>>>(
        src_ids, dst_ids, Wm, a_src, a_dst, rel_feat, a_rel);
    mark_src_kernel<<<(E_EDGES + 255) / 256, 256>>>(edge_index);
    compact_kernel<<<(N_NODES + 255) / 256, 256>>>();
    split_fused_kernel<<<SPLITA_BLOCKS + SPLITB_BLOCKS + FILL_BLOCKS, 256>>>(
        node_emb, Wm, edge_index);

    dim3 ggrid(NT_N, NT_M);
    gemm_mma_kernel<<<ggrid, 256, SM_TOT>>>();

    agg_kernel<<<(MAX_OUT * 32 + 255) / 256, 256>>>(edge_index, edge_type);
    distmult_kernel<<<(BATCH * 32 + 255) / 256, 256>>>(bias, rel_emb,
                                                       src_ids, rel_ids, dst_ids, out);
}